// round 8
// baseline (speedup 1.0000x reference)
#include <cuda_runtime.h>
#include <math.h>

// ---------------- problem constants ----------------
#define N_TOK 16384
#define NX    16383
#define DIMF  512
#define NH    8
#define DH    64
#define ML    256      // landmarks
#define QKV3  1536

typedef unsigned long long ull;

__device__ __forceinline__ ull ffma2(ull a, ull b, ull c){
    ull d; asm("fma.rn.f32x2 %0,%1,%2,%3;" : "=l"(d) : "l"(a), "l"(b), "l"(c)); return d;
}
__device__ __forceinline__ ull pack2(float x, float y){
    ull d; asm("mov.b64 %0,{%1,%2};" : "=l"(d) : "f"(x), "f"(y)); return d;
}
__device__ __forceinline__ float2 unpack2(ull v){
    float2 r; asm("mov.b64 {%0,%1},%2;" : "=f"(r.x), "=f"(r.y) : "l"(v)); return r;
}

// ---------------- scratch (device globals; ~185 MB total) ----------------
__device__ float g_h   [N_TOK*DIMF];
__device__ float g_qkv [N_TOK*QKV3];        // q|k|v (q slot reused for attn out)
__device__ float g_s3h [2*ML*N_TOK];        // LN output, then 2-head attn3 raw scores
__device__ float g_sm  [2*ML];              // softmax row max
__device__ float g_srv [2*ML];              // softmax row 1/sum
__device__ float g_ql  [NH*ML*DH];
__device__ float g_kl  [NH*ML*DH];
__device__ float g_a2  [NH*ML*ML];
__device__ float g_z   [NH*ML*ML];
__device__ float g_z2  [NH*ML*ML];
__device__ float g_xz  [NH*ML*ML];
__device__ float g_t1  [NH*ML*ML];
__device__ float g_t2b [NH*ML*ML];
__device__ float g_part[64*ML*DH];
__device__ float g_a3v [NH*ML*DH];
__device__ float g_W   [NH*ML*DH];
__device__ float g_scal[2];

// ====== 128x128x16 GEMM, 8x8 microtile, FFMA2, register-prefetch pipeline ======
#define TM 128
#define TN 128
#define TK 16

template<bool TRANSB, bool BIAS, bool RELU, bool ACCUM, bool QSCALE, bool DIAGB>
__global__ __launch_bounds__(256,2)
void gemm128_kernel(const float* __restrict__ A, const float* __restrict__ B,
                    const float* __restrict__ bias, float* __restrict__ C,
                    int Mm, int Nn, int Kk, int lda, int ldb, int ldc,
                    long sA, long sB, long sC,
                    float alpha, float dbeta, float bsign)
{
    __shared__ float As[TK][TM+4];
    __shared__ float Bs[TK][TN+4];
    int z = blockIdx.z;
    const float* Ab = A + (long)z * sA;
    const float* Bb = B + (long)z * sB;
    float* Cb = C + (long)z * sC;
    int m0 = blockIdx.y * TM;
    int n0 = blockIdx.x * TN;
    int tid = threadIdx.x;
    int tx = tid & 15, ty = tid >> 4;

    // per-thread load coordinates (fixed across k-iters)
    int aM[2], aKq[2];
    int bI0[2], bI1[2];   // TRANSB: n,kq ; else: kk,nq
#pragma unroll
    for (int l=0;l<2;l++){
        int i = tid + l*256;
        aM[l]  = i >> 2; aKq[l] = i & 3;
        if (TRANSB) { bI0[l] = i >> 2; bI1[l] = i & 3; }
        else        { bI0[l] = i >> 5; bI1[l] = i & 31; }
    }

    float4 ra[2], rb[2];

#define LOAD_TILE(KT)                                                          \
    {                                                                          \
        _Pragma("unroll")                                                      \
        for (int l=0;l<2;l++){                                                 \
            int gm = m0 + aM[l], gk = (KT) + aKq[l]*4;                         \
            if (gm < Mm) ra[l] = *reinterpret_cast<const float4*>(&Ab[(long)gm*lda + gk]); \
            else ra[l] = make_float4(0.f,0.f,0.f,0.f);                         \
        }                                                                      \
        _Pragma("unroll")                                                      \
        for (int l=0;l<2;l++){                                                 \
            if (TRANSB) {                                                      \
                int gn = n0 + bI0[l], gk = (KT) + bI1[l]*4;                    \
                rb[l] = *reinterpret_cast<const float4*>(&Bb[(long)gn*ldb + gk]); \
            } else {                                                           \
                int gk = (KT) + bI0[l], gn = n0 + bI1[l]*4;                    \
                rb[l] = *reinterpret_cast<const float4*>(&Bb[(long)gk*ldb + gn]); \
                if (DIAGB) {                                                   \
                    rb[l].x = dbeta*((gk==gn+0)?1.f:0.f) + bsign*rb[l].x;      \
                    rb[l].y = dbeta*((gk==gn+1)?1.f:0.f) + bsign*rb[l].y;      \
                    rb[l].z = dbeta*((gk==gn+2)?1.f:0.f) + bsign*rb[l].z;      \
                    rb[l].w = dbeta*((gk==gn+3)?1.f:0.f) + bsign*rb[l].w;      \
                }                                                              \
            }                                                                  \
        }                                                                      \
    }

#define STORE_TILE()                                                           \
    {                                                                          \
        _Pragma("unroll")                                                      \
        for (int l=0;l<2;l++){                                                 \
            int m = aM[l], kq = aKq[l];                                        \
            As[kq*4+0][m] = ra[l].x;                                           \
            As[kq*4+1][m] = ra[l].y;                                           \
            As[kq*4+2][m] = ra[l].z;                                           \
            As[kq*4+3][m] = ra[l].w;                                           \
        }                                                                      \
        _Pragma("unroll")                                                      \
        for (int l=0;l<2;l++){                                                 \
            if (TRANSB) {                                                      \
                int n = bI0[l], kq = bI1[l];                                   \
                Bs[kq*4+0][n] = rb[l].x;                                       \
                Bs[kq*4+1][n] = rb[l].y;                                       \
                Bs[kq*4+2][n] = rb[l].z;                                       \
                Bs[kq*4+3][n] = rb[l].w;                                       \
            } else {                                                           \
                *reinterpret_cast<float4*>(&Bs[bI0[l]][bI1[l]*4]) = rb[l];     \
            }                                                                  \
        }                                                                      \
    }

    ull acc2[8][4];
#pragma unroll
    for (int i=0;i<8;i++)
#pragma unroll
        for (int j=0;j<4;j++) acc2[i][j]=0ull;

    LOAD_TILE(0);
    for (int kt = 0; kt < Kk; kt += TK) {
        STORE_TILE();
        __syncthreads();
        if (kt + TK < Kk) LOAD_TILE(kt + TK);   // LDGs in flight during compute
#pragma unroll
        for (int kk = 0; kk < TK; kk++) {
            float4 a0 = *reinterpret_cast<const float4*>(&As[kk][ty*8]);
            float4 a1 = *reinterpret_cast<const float4*>(&As[kk][ty*8+4]);
            const ulonglong2* bp = reinterpret_cast<const ulonglong2*>(&Bs[kk][tx*8]);
            ulonglong2 u0 = bp[0], u1 = bp[1];
            ull b2[4] = {u0.x, u0.y, u1.x, u1.y};
            float a[8] = {a0.x,a0.y,a0.z,a0.w,a1.x,a1.y,a1.z,a1.w};
#pragma unroll
            for (int i=0;i<8;i++) {
                ull ad = pack2(a[i], a[i]);
#pragma unroll
                for (int j=0;j<4;j++) acc2[i][j] = ffma2(ad, b2[j], acc2[i][j]);
            }
        }
        __syncthreads();
    }
#undef LOAD_TILE
#undef STORE_TILE
    // ---- epilogue ----
#pragma unroll
    for (int i=0;i<8;i++) {
        int gm = m0 + ty*8 + i;
        if (gm >= Mm) continue;
        long rowoff = (long)gm*ldc;
#pragma unroll
        for (int j2=0;j2<4;j2++) {
            float2 p = unpack2(acc2[i][j2]);
            float vv[2] = {p.x, p.y};
#pragma unroll
            for (int s=0;s<2;s++) {
                int gn = n0 + tx*8 + j2*2 + s;
                float v = alpha * vv[s];
                if (QSCALE && gn < 512) v *= 0.125f;
                if (BIAS) v += bias[gn];
                if (RELU) v = fmaxf(v, 0.f);
                long idx = rowoff + gn;
                if (ACCUM) Cb[idx] += v; else Cb[idx] = v;
            }
        }
    }
}

// ================= 64x64x16 GEMM (a3v / W paths, split-K, EXPA) =================
#define BM 64
#define BN 64
#define BK 16

template<bool TRANSB, bool ACCUM, bool EXPA>
__global__ __launch_bounds__(256)
void gemm_kernel(const float* __restrict__ A, const float* __restrict__ B,
                 float* __restrict__ C,
                 const float* __restrict__ mu,  const float* __restrict__ rstd,
                 int Mm, int Nn, int Kk, int lda, int ldb, int ldc,
                 long sA, long sB, long sC, int kchunks, float alpha)
{
    __shared__ float As[BK][BM+1];
    __shared__ float Bs[BK][BN+1];
    int z = blockIdx.z;
    int batch = z / kchunks;
    int chunk = z - batch*kchunks;
    const float* Ab = A + (long)batch * sA;
    const float* Bb = B + (long)batch * sB;
    float* Cb = C + (long)z * sC;
    int kPer   = Kk / kchunks;
    int kstart = chunk * kPer;
    int m0 = blockIdx.y * BM;
    int n0 = blockIdx.x * BN;
    int tid = threadIdx.x;
    int tx = tid & 15, ty = tid >> 4;
    float acc[4][4];
#pragma unroll
    for (int i=0;i<4;i++)
#pragma unroll
        for (int j=0;j<4;j++) acc[i][j]=0.f;

    for (int kt = kstart; kt < kstart + kPer; kt += BK) {
#pragma unroll
        for (int l = 0; l < 4; l++) {
            int i  = tid + l*256;
            int m  = i >> 4, kk = i & 15;
            int gm = m0 + m, gk = kt + kk;
            float v = 0.f;
            if (gm < Mm && gk < Kk) {
                v = Ab[(long)gm*lda + gk];
                if (EXPA) v = __expf(v - mu[(long)batch*Mm + gm]) * rstd[(long)batch*Mm + gm];
            }
            As[kk][m] = v;
        }
#pragma unroll
        for (int l = 0; l < 4; l++) {
            int i = tid + l*256;
            float v; int kk, n;
            if (TRANSB) {
                n = i >> 4; kk = i & 15;
                int gn = n0 + n, gk = kt + kk;
                v = (gn < Nn && gk < Kk) ? Bb[(long)gn*ldb + gk] : 0.f;
            } else {
                kk = i >> 6; n = i & 63;
                int gn = n0 + n, gk = kt + kk;
                v = (gn < Nn && gk < Kk) ? Bb[(long)gk*ldb + gn] : 0.f;
            }
            Bs[kk][n] = v;
        }
        __syncthreads();
#pragma unroll
        for (int kk = 0; kk < BK; kk++) {
            float a[4], b[4];
#pragma unroll
            for (int i=0;i<4;i++) a[i] = As[kk][ty*4+i];
#pragma unroll
            for (int j=0;j<4;j++) b[j] = Bs[kk][tx*4+j];
#pragma unroll
            for (int i=0;i<4;i++)
#pragma unroll
                for (int j=0;j<4;j++) acc[i][j] += a[i]*b[j];
        }
        __syncthreads();
    }
#pragma unroll
    for (int i=0;i<4;i++) {
        int gm = m0 + ty*4 + i;
        if (gm >= Mm) continue;
#pragma unroll
        for (int j=0;j<4;j++) {
            int gn = n0 + tx*4 + j;
            if (gn >= Nn) continue;
            float v = alpha * acc[i][j];
            long idx = (long)gm*ldc + gn;
            if (ACCUM) Cb[idx] += v; else Cb[idx] = v;
        }
    }
}

// ---------------- small kernels ----------------
__global__ void copy_cls_kernel(const float* __restrict__ c, float* __restrict__ h){
    int i = blockIdx.x*256 + threadIdx.x;
    if (i < DIMF) h[i] = c[i];
}

// full layernorm: y = (x - mu)*rstd*w + b
__global__ void layernorm_kernel(const float* __restrict__ x, const float* __restrict__ w,
                                 const float* __restrict__ b, float* __restrict__ y)
{
    __shared__ float red[256];
    int row = blockIdx.x, tid = threadIdx.x;
    const float* xr = x + (long)row*DIMF;
    float v0 = xr[tid], v1 = xr[tid+256];
    red[tid] = v0+v1; __syncthreads();
    for (int s=128;s;s>>=1){ if(tid<s) red[tid]+=red[tid+s]; __syncthreads(); }
    float m = red[0]*(1.f/512.f); __syncthreads();
    float d0 = v0-m, d1 = v1-m;
    red[tid] = d0*d0+d1*d1; __syncthreads();
    for (int s=128;s;s>>=1){ if(tid<s) red[tid]+=red[tid+s]; __syncthreads(); }
    float rstd = rsqrtf(red[0]*(1.f/512.f) + 1e-5f);
    float* yr = y + (long)row*DIMF;
    yr[tid]     = d0*rstd*w[tid]     + b[tid];
    yr[tid+256] = d1*rstd*w[tid+256] + b[tid+256];
}

__global__ void landmark_kernel(const float* __restrict__ qkv,
                                float* __restrict__ ql, float* __restrict__ kl)
{
    int b = blockIdx.x; int hd = b >> 8; int j = b & 255;
    int d = threadIdx.x;
    float sq = 0.f, sk = 0.f;
    long base = (long)(j*64)*QKV3 + hd*64 + d;
#pragma unroll 4
    for (int i=0;i<64;i++){ sq += qkv[base + (long)i*QKV3]; sk += qkv[base + (long)i*QKV3 + 512]; }
    ql[((hd<<8)+j)*64 + d] = sq*(1.f/64.f);
    kl[((hd<<8)+j)*64 + d] = sk*(1.f/64.f);
}

__global__ void attn2_kernel(const float* __restrict__ ql, const float* __restrict__ kl,
                             float* __restrict__ out)
{
    __shared__ float qrow[64];
    __shared__ float red[256];
    int b = blockIdx.x; int hd = b >> 8; int j = b & 255;
    int tid = threadIdx.x;
    if (tid < 64) qrow[tid] = ql[((hd<<8)+j)*64 + tid];
    __syncthreads();
    const float* krow = kl + ((long)((hd<<8)+tid))*64;
    float acc = 0.f;
#pragma unroll 8
    for (int d=0; d<64; d++) acc += qrow[d]*krow[d];
    red[tid]=acc; __syncthreads();
    for (int s=128;s;s>>=1){ if(tid<s) red[tid]=fmaxf(red[tid],red[tid+s]); __syncthreads(); }
    float mx = red[0]; __syncthreads();
    float e = expf(acc - mx);
    red[tid]=e; __syncthreads();
    for (int s=128;s;s>>=1){ if(tid<s) red[tid]+=red[tid+s]; __syncthreads(); }
    out[((long)((hd<<8)+j))*256 + tid] = e * (1.f/red[0]);
}

__global__ void zero_scal_kernel(float* s){ if (threadIdx.x < 2) s[threadIdx.x] = 0.f; }

__global__ void pinv_max_kernel(const float* __restrict__ x, float* __restrict__ scal)
{
    __shared__ float red[256];
    int b = blockIdx.x, tid = threadIdx.x;
    float s;
    if (b < 2048) { int hd=b>>8, i=b&255; s = x[(((long)(hd<<8)+i)<<8) + tid]; }
    else { int bb=b-2048; int hd=bb>>8, j=bb&255; s = x[(((long)(hd<<8)+tid)<<8) + j]; }
    red[tid]=s; __syncthreads();
    for (int st=128;st;st>>=1){ if(tid<st) red[tid]+=red[tid+st]; __syncthreads(); }
    if (tid==0) atomicMax((int*)&scal[b<2048?0:1], __float_as_int(red[0]));
}

__global__ void zinit_kernel(const float* __restrict__ x, const float* __restrict__ scal,
                             float* __restrict__ z)
{
    int b = blockIdx.x; int hd=b>>8, i=b&255; int j=threadIdx.x;
    float inv = 1.f/(scal[0]*scal[1]);
    z[(((long)(hd<<8)+i)<<8)+j] = x[(((long)(hd<<8)+j)<<8)+i] * inv;
}

// softmax row stats only: max + 1/sum(exp(x-max))
__global__ void softmax_stats_kernel(const float* __restrict__ s, int n,
                                     float* __restrict__ m_out, float* __restrict__ rv_out)
{
    __shared__ float red[256];
    long base = (long)blockIdx.x * n;
    int tid = threadIdx.x;
    float mx = -1e30f;
    for (int i=tid;i<n;i+=256) mx = fmaxf(mx, s[base+i]);
    red[tid]=mx; __syncthreads();
    for (int st=128;st;st>>=1){ if(tid<st) red[tid]=fmaxf(red[tid],red[tid+st]); __syncthreads(); }
    mx = red[0]; __syncthreads();
    float sum=0.f;
    for (int i=tid;i<n;i+=256) sum += __expf(s[base+i]-mx);
    red[tid]=sum; __syncthreads();
    for (int st=128;st;st>>=1){ if(tid<st) red[tid]+=red[tid+st]; __syncthreads(); }
    if (tid==0){ m_out[blockIdx.x]=mx; rv_out[blockIdx.x]=1.f/red[0]; }
}

__global__ void reduce_part_kernel(const float* __restrict__ part, float* __restrict__ out,
                                   int chunks, int sz, int nb)
{
    long idx = (long)blockIdx.x*256 + threadIdx.x;
    if (idx >= (long)nb*sz) return;
    int b = (int)(idx / sz); int r = (int)(idx - (long)b*sz);
    float s = 0.f;
    for (int c=0;c<chunks;c++) s += part[((long)(b*chunks+c))*sz + r];
    out[idx] = s;
}

// fused attn1 @ W : 32 tokens x 1 head per block; f32x2 math; in-place into qkv q-slot.
#define KLS_STRIDE 66
__global__ void attn1_kernel(float* __restrict__ qkv, const float* __restrict__ kl,
                             const float* __restrict__ W)
{
    extern __shared__ float sm[];
    float* kls = sm;                       // 256*66
    float* qs  = sm + 256*KLS_STRIDE;      // 32*64
    float* ss  = qs + 32*64;               // 32*256
    int hd = blockIdx.y;
    int i0 = blockIdx.x * 32;
    int tid = threadIdx.x;
    for (int idx = tid; idx < 256*64; idx += 256) {
        int c = idx >> 6, d = idx & 63;
        kls[c*KLS_STRIDE+d] = kl[((long)((hd<<8)+c))*64 + d];
    }
    for (int idx = tid; idx < 32*64; idx += 256) {
        int r = idx >> 6, d = idx & 63;
        qs[idx] = qkv[(long)(i0+r)*QKV3 + hd*64 + d];
    }
    __syncthreads();
    {
        int c = tid;
        const ull* k2 = reinterpret_cast<const ull*>(&kls[c*KLS_STRIDE]);
        for (int r = 0; r < 32; r++) {
            const ull* q2 = reinterpret_cast<const ull*>(&qs[r*64]);
            ull acc2 = 0ull;
#pragma unroll 8
            for (int d2 = 0; d2 < 32; d2++) acc2 = ffma2(q2[d2], k2[d2], acc2);
            float2 p = unpack2(acc2);
            ss[r*256+c] = p.x + p.y;
        }
    }
    __syncthreads();
    {
        int w = tid >> 5, lane = tid & 31;
        for (int r = w*4; r < w*4+4; r++) {
            float mx = -1e30f;
#pragma unroll
            for (int k=0;k<8;k++) mx = fmaxf(mx, ss[r*256 + lane + 32*k]);
            for (int o=16;o;o>>=1) mx = fmaxf(mx, __shfl_xor_sync(0xffffffffu, mx, o));
            float sum = 0.f;
#pragma unroll
            for (int k=0;k<8;k++){ float e = __expf(ss[r*256+lane+32*k]-mx); ss[r*256+lane+32*k]=e; sum+=e; }
            for (int o=16;o;o>>=1) sum += __shfl_xor_sync(0xffffffffu, sum, o);
            float inv = 1.f/sum;
#pragma unroll
            for (int k=0;k<8;k++) ss[r*256+lane+32*k] *= inv;
        }
    }
    __syncthreads();
    {
        int d = tid & 63, rb = tid >> 6;
        ull acc2[8];
#pragma unroll
        for (int j=0;j<8;j++) acc2[j]=0ull;
        const float* Wh = W + (long)hd*ML*DH;
        for (int c2 = 0; c2 < 128; c2++) {
            float w0 = Wh[(2*c2)*64 + d];
            float w1 = Wh[(2*c2+1)*64 + d];
            ull wp = pack2(w0, w1);
#pragma unroll
            for (int j=0;j<8;j++) {
                ull s2 = *reinterpret_cast<const ull*>(&ss[(rb + 4*j)*256 + 2*c2]);
                acc2[j] = ffma2(s2, wp, acc2[j]);
            }
        }
#pragma unroll
        for (int j=0;j<8;j++) {
            float2 p = unpack2(acc2[j]);
            int r = rb + 4*j;
            qkv[(long)(i0+r)*QKV3 + hd*64 + d] = p.x + p.y;
        }
    }
}

// depthwise residual conv over sequence: qkv q-slot += conv(v, res_k)
__global__ void conv_kernel(float* __restrict__ qkv, const float* __restrict__ rk)
{
    __shared__ float rks[NH*33];
    int tid = threadIdx.x;
    for (int i = tid; i < NH*33; i += 256) rks[i] = rk[i];
    __syncthreads();
    long idx = (long)blockIdx.x*256 + tid;
    int i = (int)(idx >> 9); int col = (int)(idx & 511); int hd = col >> 6;
    long addr = (long)i*QKV3 + col;
    float acc = qkv[addr];
#pragma unroll
    for (int t=0;t<33;t++){
        int ii = i + t - 16;
        if (ii >= 0 && ii < N_TOK)
            acc += rks[hd*33+t] * qkv[(long)ii*QKV3 + 1024 + col];
    }
    qkv[addr] = acc;
}

// final: LN on row 0 -> clf -> sigmoid -> cumprod survival
__global__ void final_kernel(const float* __restrict__ h, const float* __restrict__ nw,
                             const float* __restrict__ nb, const float* __restrict__ cw,
                             const float* __restrict__ cb, float* __restrict__ out)
{
    __shared__ float red[512];
    __shared__ float xn[512];
    __shared__ float lg[4];
    int tid = threadIdx.x;
    float v = h[tid];
    red[tid]=v; __syncthreads();
    for (int s=256;s;s>>=1){ if(tid<s) red[tid]+=red[tid+s]; __syncthreads(); }
    float mu = red[0]*(1.f/512.f); __syncthreads();
    float d = v-mu;
    red[tid]=d*d; __syncthreads();
    for (int s=256;s;s>>=1){ if(tid<s) red[tid]+=red[tid+s]; __syncthreads(); }
    float rstd = rsqrtf(red[0]*(1.f/512.f) + 1e-5f);
    xn[tid] = d*rstd*nw[tid] + nb[tid];
    __syncthreads();
    if (tid < 128) {
        int c = tid >> 5, lane = tid & 31;
        float s = 0.f;
        for (int k=lane;k<512;k+=32) s += xn[k]*cw[k*4+c];
        for (int o=16;o;o>>=1) s += __shfl_xor_sync(0xffffffffu, s, o);
        if (lane==0) lg[c] = s + cb[c];
    }
    __syncthreads();
    if (tid==0) {
        float S = 1.f;
        for (int c=0;c<4;c++){
            float hz = 1.f/(1.f+expf(-lg[c]));
            out[c] = hz;
            S *= (1.f - hz);
            out[4+c] = S;
        }
    }
}

// ---------------- host launch ----------------
#define GEMM128(TB,BI,RE,AC,QS,DG, grid, A,B,bias,C, M,N,K, lda,ldb,ldc, sA,sB,sC, al,db,bs) \
    gemm128_kernel<TB,BI,RE,AC,QS,DG><<<grid, 256>>>(A,B,bias,C,M,N,K,lda,ldb,ldc,(long)(sA),(long)(sB),(long)(sC),al,db,bs)

#define GEMM64(TB,AC,EX, grid, A,B,C, mu,rstd, M,N,K, lda,ldb,ldc, sA,sB,sC, kch, al) \
    gemm_kernel<TB,AC,EX><<<grid, 256>>>(A,B,C,mu,rstd,M,N,K,lda,ldb,ldc,(long)(sA),(long)(sB),(long)(sC),kch,al)

extern "C" void kernel_launch(void* const* d_in, const int* in_sizes, int n_in,
                              void* d_out, int out_size)
{
    const float* x     = (const float*)d_in[0];
    const float* fc_w  = (const float*)d_in[1];
    const float* fc_b  = (const float*)d_in[2];
    const float* cls   = (const float*)d_in[3];
    const float* Lp[2][6];
    for (int l=0;l<2;l++) for (int k=0;k<6;k++) Lp[l][k] = (const float*)d_in[4 + l*6 + k];
    const float* norm_w = (const float*)d_in[16];
    const float* norm_b = (const float*)d_in[17];
    const float* clf_w  = (const float*)d_in[18];
    const float* clf_b  = (const float*)d_in[19];
    float* out = (float*)d_out;
    const float* F0 = 0;

    float *ph,*pqkv,*ps3,*psm,*psrv,*pql,*pkl,*pa2,*pz,*pz2,*pxz,*pt1,*pt2,*ppart,*pa3v,*pW,*pscal;
    cudaGetSymbolAddress((void**)&ph,   g_h);
    cudaGetSymbolAddress((void**)&pqkv, g_qkv);
    cudaGetSymbolAddress((void**)&ps3,  g_s3h);
    cudaGetSymbolAddress((void**)&psm,  g_sm);
    cudaGetSymbolAddress((void**)&psrv, g_srv);
    cudaGetSymbolAddress((void**)&pql,  g_ql);
    cudaGetSymbolAddress((void**)&pkl,  g_kl);
    cudaGetSymbolAddress((void**)&pa2,  g_a2);
    cudaGetSymbolAddress((void**)&pz,   g_z);
    cudaGetSymbolAddress((void**)&pz2,  g_z2);
    cudaGetSymbolAddress((void**)&pxz,  g_xz);
    cudaGetSymbolAddress((void**)&pt1,  g_t1);
    cudaGetSymbolAddress((void**)&pt2,  g_t2b);
    cudaGetSymbolAddress((void**)&ppart,g_part);
    cudaGetSymbolAddress((void**)&pa3v, g_a3v);
    cudaGetSymbolAddress((void**)&pW,   g_W);
    cudaGetSymbolAddress((void**)&pscal,g_scal);

    cudaFuncSetAttribute(attn1_kernel, cudaFuncAttributeMaxDynamicSharedMemorySize, 110592);

    // h[1:] = relu(x @ fc_w + fc_b); h[0] = cls
    GEMM128(false,true,true,false,false,false, dim3(4,128,1),
            x, fc_w, fc_b, ph+DIMF, NX,512,1024, 1024,512,512, 0,0,0, 1.f,0.f,1.f);
    copy_cls_kernel<<<2,256>>>(cls, ph);

    for (int l=0;l<2;l++) {
        const float *nw=Lp[l][0], *nb=Lp[l][1], *qw=Lp[l][2],
                    *ow=Lp[l][3], *ob=Lp[l][4], *rk=Lp[l][5];

        // full LN into ps3 (free until attn3 scores), then plain qkv GEMM (q pre-scaled 1/8)
        layernorm_kernel<<<N_TOK,256>>>(ph, nw, nb, ps3);
        GEMM128(false,false,false,false,true,false, dim3(12,128,1),
                ps3, qw, F0, pqkv, N_TOK,QKV3,512, 512,QKV3,QKV3, 0,0,0, 1.f,0.f,1.f);
        landmark_kernel<<<2048,64>>>(pqkv, pql, pkl);
        attn2_kernel<<<2048,256>>>(pql, pkl, pa2);

        // pinv init
        zero_scal_kernel<<<1,32>>>(pscal);
        pinv_max_kernel<<<4096,256>>>(pa2, pscal);
        zinit_kernel<<<2048,256>>>(pa2, pscal, pz);
        float* zc = pz; float* zo = pz2;
        for (int it=0; it<6; it++) {
            GEMM128(false,false,false,false,false,false, dim3(2,2,8),
                    pa2, zc, F0, pxz, 256,256,256, 256,256,256, 65536,65536,65536, 1.f,0.f,1.f);
            GEMM128(false,false,false,false,false,true, dim3(2,2,8),
                    pxz, pxz, F0, pt1, 256,256,256, 256,256,256, 65536,65536,65536, 1.f,7.f,-1.f);
            GEMM128(false,false,false,false,false,true, dim3(2,2,8),
                    pxz, pt1, F0, pt2, 256,256,256, 256,256,256, 65536,65536,65536, 1.f,15.f,-1.f);
            GEMM128(false,false,false,false,false,true, dim3(2,2,8),
                    zc, pt2, F0, zo, 256,256,256, 256,256,256, 65536,65536,65536, 0.25f,13.f,-1.f);
            float* tmp=zc; zc=zo; zo=tmp;
        }

        // attn3 @ v, 2 heads per batch; softmax fused into a3v A-load
        for (int h0=0; h0<NH; h0+=2) {
            GEMM128(true,false,false,false,false,false, dim3(128,2,2),
                    pql + h0*ML*DH, pqkv+512+h0*64, F0, ps3,
                    256,N_TOK,64, 64,QKV3,N_TOK, ML*DH,64,(long)ML*N_TOK, 1.f,0.f,1.f);
            softmax_stats_kernel<<<2*ML,256>>>(ps3, N_TOK, psm, psrv);
            GEMM64(false,false,true, dim3(1,4,2*32),
                   ps3, pqkv+1024+h0*64, ppart, psm,psrv,
                   256,64,N_TOK, N_TOK,QKV3,64, (long)ML*N_TOK,64,ML*DH, 32, 1.f);
            reduce_part_kernel<<<(2*ML*DH+255)/256,256>>>(ppart, pa3v + h0*ML*DH, 32, ML*DH, 2);
        }
        // W = pinv @ a3v  (batched over heads, split-K 4)
        GEMM64(false,false,false, dim3(1,4,8*4),
               zc, pa3v, ppart, F0,F0,
               256,64,256, 256,64,64, 65536,ML*DH,ML*DH, 4, 1.f);
        reduce_part_kernel<<<(NH*ML*DH+255)/256,256>>>(ppart, pW, 4, ML*DH, NH);

        // fused: q-slot of qkv <- softmax(q @ k_l^T) @ W
        attn1_kernel<<<dim3(512,NH),256,110592>>>(pqkv, pkl, pW);
        // + depthwise residual conv of v
        conv_kernel<<<(N_TOK*DIMF)/256,256>>>(pqkv, rk);
        // h += attn_out @ out_w + out_b
        GEMM128(false,true,false,true,false,false, dim3(4,128,1),
                pqkv, ow, ob, ph, N_TOK,512,512, 1536,512,512, 0,0,0, 1.f,0.f,1.f);
    }

    final_kernel<<<1,512>>>(ph, norm_w, norm_b, clf_w, clf_b, out);
}

// round 10
// speedup vs baseline: 1.7497x; 1.7497x over previous
#include <cuda_runtime.h>
#include <math.h>

// ---------------- problem constants ----------------
#define N_TOK 16384
#define NX    16383
#define DIMF  512
#define NH    8
#define DH    64
#define ML    256      // landmarks
#define QKV3  1536

typedef unsigned long long ull;

__device__ __forceinline__ ull ffma2(ull a, ull b, ull c){
    ull d; asm("fma.rn.f32x2 %0,%1,%2,%3;" : "=l"(d) : "l"(a), "l"(b), "l"(c)); return d;
}
__device__ __forceinline__ ull pack2(float x, float y){
    ull d; asm("mov.b64 %0,{%1,%2};" : "=l"(d) : "f"(x), "f"(y)); return d;
}
__device__ __forceinline__ float2 unpack2(ull v){
    float2 r; asm("mov.b64 {%0,%1},%2;" : "=f"(r.x), "=f"(r.y) : "l"(v)); return r;
}
__device__ __forceinline__ unsigned smem_u32(const void* p){
    unsigned a; asm("{ .reg .u64 t; cvta.to.shared.u64 t, %1; cvt.u32.u64 %0, t; }" : "=r"(a) : "l"(p));
    return a;
}
__device__ __forceinline__ void cp_async16(unsigned saddr, const void* gaddr){
    asm volatile("cp.async.cg.shared.global [%0], [%1], 16;" :: "r"(saddr), "l"(gaddr));
}
#define CP_COMMIT() asm volatile("cp.async.commit_group;")
#define CP_WAIT(N)  asm volatile("cp.async.wait_group %0;" :: "n"(N))

// ---------------- scratch (device globals; ~185 MB total) ----------------
__device__ float g_h   [N_TOK*DIMF];
__device__ float g_qkv [N_TOK*QKV3];        // q|k|v (q slot reused for attn out)
__device__ float g_s3h [2*ML*N_TOK];        // LN staging, then 2-head attn3 raw scores
__device__ float g_sm  [2*ML];              // softmax row max
__device__ float g_srv [2*ML];              // softmax row 1/sum
__device__ float g_ql  [NH*ML*DH];
__device__ float g_kl  [NH*ML*DH];
__device__ float g_a2  [NH*ML*ML];
__device__ float g_z   [NH*ML*ML];
__device__ float g_z2  [NH*ML*ML];
__device__ float g_xz  [NH*ML*ML];
__device__ float g_t1  [NH*ML*ML];
__device__ float g_t2b [NH*ML*ML];
__device__ float g_part[64*ML*DH];
__device__ float g_a3v [NH*ML*DH];
__device__ float g_W   [NH*ML*DH];
__device__ float g_scal[2];

#define TM 128
#define TN 128
#define TK 16

// ====== pipelined non-TRANSB 128x128x16 GEMM: cp.async double buffer ======
// A stored untransposed [m][20]; B [k][132]. K multiple of 16, N covered by grid,
// lda/ldb/ldc multiples of 4, 16B-aligned bases. M edge guarded (garbage rows unused).
template<bool BIAS, bool RELU, bool ACCUM, bool QSCALE>
__global__ __launch_bounds__(256)
void gemm128p_kernel(const float* __restrict__ A, const float* __restrict__ B,
                     const float* __restrict__ bias, float* __restrict__ C,
                     int Mm, int Nn, int Kk, int lda, int ldb, int ldc,
                     long sA, long sB, long sC)
{
    __shared__ float As[2][TM][20];
    __shared__ float Bs[2][TK][TN+4];
    int z = blockIdx.z;
    const float* Ab = A + (long)z * sA;
    const float* Bb = B + (long)z * sB;
    float* Cb = C + (long)z * sC;
    int m0 = blockIdx.y * TM;
    int n0 = blockIdx.x * TN;
    int tid = threadIdx.x;
    int tx = tid & 15, ty = tid >> 4;

    // fixed per-thread copy coordinates (2 chunks of 16B for A, 2 for B)
    int aM[2], aKq[2], bKK[2], bNq[2];
#pragma unroll
    for (int l=0;l<2;l++){
        int i = tid + l*256;
        aM[l] = i >> 2;  aKq[l] = i & 3;
        bKK[l] = i >> 5; bNq[l] = i & 31;
    }

    ull acc2[8][4];
#pragma unroll
    for (int i=0;i<8;i++)
#pragma unroll
        for (int j=0;j<4;j++) acc2[i][j]=0ull;

#define ISSUE_TILE(KT, BUF)                                                    \
    {                                                                          \
        _Pragma("unroll")                                                      \
        for (int l=0;l<2;l++){                                                 \
            int gm = m0 + aM[l], gk = (KT) + aKq[l]*4;                         \
            if (gm < Mm)                                                       \
                cp_async16(smem_u32(&As[BUF][aM[l]][aKq[l]*4]),                \
                           &Ab[(long)gm*lda + gk]);                            \
        }                                                                      \
        _Pragma("unroll")                                                      \
        for (int l=0;l<2;l++){                                                 \
            int gk = (KT) + bKK[l], gn = n0 + bNq[l]*4;                        \
            cp_async16(smem_u32(&Bs[BUF][bKK[l]][bNq[l]*4]),                   \
                       &Bb[(long)gk*ldb + gn]);                                \
        }                                                                      \
        CP_COMMIT();                                                           \
    }

    int kTiles = Kk / TK;
    ISSUE_TILE(0, 0);
    for (int t = 0; t < kTiles; t++) {
        int buf = t & 1;
        if (t + 1 < kTiles) { ISSUE_TILE((t+1)*TK, buf^1); CP_WAIT(1); }
        else                { CP_WAIT(0); }
        __syncthreads();
#pragma unroll
        for (int q = 0; q < 4; q++) {
#pragma unroll
            for (int kk2 = 0; kk2 < 4; kk2++) {
                int kk = q*4 + kk2;
                const ulonglong2* bp = reinterpret_cast<const ulonglong2*>(&Bs[buf][kk][tx*8]);
                ulonglong2 u0 = bp[0], u1 = bp[1];
                ull b2[4] = {u0.x, u0.y, u1.x, u1.y};
#pragma unroll
                for (int i=0;i<8;i++) {
                    float av = As[buf][ty*8+i][kk];
                    ull ad = pack2(av, av);
#pragma unroll
                    for (int j=0;j<4;j++) acc2[i][j] = ffma2(ad, b2[j], acc2[i][j]);
                }
            }
        }
        __syncthreads();
    }
#undef ISSUE_TILE
    // ---- epilogue ----
#pragma unroll
    for (int i=0;i<8;i++) {
        int gm = m0 + ty*8 + i;
        if (gm >= Mm) continue;
        long rowoff = (long)gm*ldc;
#pragma unroll
        for (int j2=0;j2<4;j2++) {
            float2 p = unpack2(acc2[i][j2]);
            float vv[2] = {p.x, p.y};
#pragma unroll
            for (int s=0;s<2;s++) {
                int gn = n0 + tx*8 + j2*2 + s;
                float v = vv[s];
                if (QSCALE && gn < 512) v *= 0.125f;
                if (BIAS) v += bias[gn];
                if (RELU) v = fmaxf(v, 0.f);
                long idx = rowoff + gn;
                if (ACCUM) Cb[idx] += v; else Cb[idx] = v;
            }
        }
    }
}

// ====== Round-7 128x128x16 GEMM (TRANSB scores path) ======
template<bool TRANSB>
__global__ __launch_bounds__(256)
void gemm128_kernel(const float* __restrict__ A, const float* __restrict__ B,
                    float* __restrict__ C,
                    int Mm, int Nn, int Kk, int lda, int ldb, int ldc,
                    long sA, long sB, long sC)
{
    __shared__ float As[TK][TM+4];
    __shared__ float Bs[TK][TN+4];
    int z = blockIdx.z;
    const float* Ab = A + (long)z * sA;
    const float* Bb = B + (long)z * sB;
    float* Cb = C + (long)z * sC;
    int m0 = blockIdx.y * TM;
    int n0 = blockIdx.x * TN;
    int tid = threadIdx.x;
    int tx = tid & 15, ty = tid >> 4;

    ull acc2[8][4];
#pragma unroll
    for (int i=0;i<8;i++)
#pragma unroll
        for (int j=0;j<4;j++) acc2[i][j]=0ull;

    for (int kt = 0; kt < Kk; kt += TK) {
#pragma unroll
        for (int l = 0; l < 2; l++) {
            int i = tid + l*256;
            int m = i >> 2, kq = i & 3;
            int gm = m0 + m, gk = kt + kq*4;
            float4 v = make_float4(0.f,0.f,0.f,0.f);
            if (gm < Mm) v = *reinterpret_cast<const float4*>(&Ab[(long)gm*lda + gk]);
            As[kq*4+0][m] = v.x;
            As[kq*4+1][m] = v.y;
            As[kq*4+2][m] = v.z;
            As[kq*4+3][m] = v.w;
        }
        if (TRANSB) {
#pragma unroll
            for (int l = 0; l < 2; l++) {
                int i = tid + l*256;
                int n = i >> 2, kq = i & 3;
                int gn = n0 + n, gk = kt + kq*4;
                float4 v = *reinterpret_cast<const float4*>(&Bb[(long)gn*ldb + gk]);
                Bs[kq*4+0][n] = v.x;
                Bs[kq*4+1][n] = v.y;
                Bs[kq*4+2][n] = v.z;
                Bs[kq*4+3][n] = v.w;
            }
        } else {
#pragma unroll
            for (int l = 0; l < 2; l++) {
                int i = tid + l*256;
                int kk = i >> 5, nq = i & 31;
                int gn = n0 + nq*4, gk = kt + kk;
                float4 v = *reinterpret_cast<const float4*>(&Bb[(long)gk*ldb + gn]);
                *reinterpret_cast<float4*>(&Bs[kk][nq*4]) = v;
            }
        }
        __syncthreads();
#pragma unroll
        for (int kk = 0; kk < TK; kk++) {
            float4 a0 = *reinterpret_cast<const float4*>(&As[kk][ty*8]);
            float4 a1 = *reinterpret_cast<const float4*>(&As[kk][ty*8+4]);
            const ulonglong2* bp = reinterpret_cast<const ulonglong2*>(&Bs[kk][tx*8]);
            ulonglong2 u0 = bp[0], u1 = bp[1];
            ull b2[4] = {u0.x, u0.y, u1.x, u1.y};
            float a[8] = {a0.x,a0.y,a0.z,a0.w,a1.x,a1.y,a1.z,a1.w};
#pragma unroll
            for (int i=0;i<8;i++) {
                ull ad = pack2(a[i], a[i]);
#pragma unroll
                for (int j=0;j<4;j++) acc2[i][j] = ffma2(ad, b2[j], acc2[i][j]);
            }
        }
        __syncthreads();
    }
#pragma unroll
    for (int i=0;i<8;i++) {
        int gm = m0 + ty*8 + i;
        if (gm >= Mm) continue;
        long rowoff = (long)gm*ldc;
#pragma unroll
        for (int j2=0;j2<4;j2++) {
            float2 p = unpack2(acc2[i][j2]);
            Cb[rowoff + n0 + tx*8 + j2*2 + 0] = p.x;
            Cb[rowoff + n0 + tx*8 + j2*2 + 1] = p.y;
        }
    }
}

// ================= 64x64x16 GEMM (pinv / a3v / W paths) =================
#define BM 64
#define BN 64
#define BK 16

template<bool TRANSB, bool ACCUM, bool DIAGB, bool EXPA>
__global__ __launch_bounds__(256)
void gemm_kernel(const float* __restrict__ A, const float* __restrict__ B,
                 float* __restrict__ C,
                 const float* __restrict__ mu,  const float* __restrict__ rstd,
                 int Mm, int Nn, int Kk, int lda, int ldb, int ldc,
                 long sA, long sB, long sC, int kchunks,
                 float alpha, float dbeta, float bsign)
{
    __shared__ float As[BK][BM+1];
    __shared__ float Bs[BK][BN+1];
    int z = blockIdx.z;
    int batch = z / kchunks;
    int chunk = z - batch*kchunks;
    const float* Ab = A + (long)batch * sA;
    const float* Bb = B + (long)batch * sB;
    float* Cb = C + (long)z * sC;
    int kPer   = Kk / kchunks;
    int kstart = chunk * kPer;
    int m0 = blockIdx.y * BM;
    int n0 = blockIdx.x * BN;
    int tid = threadIdx.x;
    int tx = tid & 15, ty = tid >> 4;
    float acc[4][4];
#pragma unroll
    for (int i=0;i<4;i++)
#pragma unroll
        for (int j=0;j<4;j++) acc[i][j]=0.f;

    for (int kt = kstart; kt < kstart + kPer; kt += BK) {
#pragma unroll
        for (int l = 0; l < 4; l++) {
            int i  = tid + l*256;
            int m  = i >> 4, kk = i & 15;
            int gm = m0 + m, gk = kt + kk;
            float v = 0.f;
            if (gm < Mm && gk < Kk) {
                v = Ab[(long)gm*lda + gk];
                if (EXPA) v = __expf(v - mu[(long)batch*Mm + gm]) * rstd[(long)batch*Mm + gm];
            }
            As[kk][m] = v;
        }
#pragma unroll
        for (int l = 0; l < 4; l++) {
            int i = tid + l*256;
            float v; int kk, n;
            if (TRANSB) {
                n = i >> 4; kk = i & 15;
                int gn = n0 + n, gk = kt + kk;
                v = (gn < Nn && gk < Kk) ? Bb[(long)gn*ldb + gk] : 0.f;
            } else {
                kk = i >> 6; n = i & 63;
                int gn = n0 + n, gk = kt + kk;
                v = (gn < Nn && gk < Kk) ? Bb[(long)gk*ldb + gn] : 0.f;
                if (DIAGB) v = dbeta*((gk==gn)?1.f:0.f) + bsign*v;
            }
            Bs[kk][n] = v;
        }
        __syncthreads();
#pragma unroll
        for (int kk = 0; kk < BK; kk++) {
            float a[4], b[4];
#pragma unroll
            for (int i=0;i<4;i++) a[i] = As[kk][ty*4+i];
#pragma unroll
            for (int j=0;j<4;j++) b[j] = Bs[kk][tx*4+j];
#pragma unroll
            for (int i=0;i<4;i++)
#pragma unroll
                for (int j=0;j<4;j++) acc[i][j] += a[i]*b[j];
        }
        __syncthreads();
    }
#pragma unroll
    for (int i=0;i<4;i++) {
        int gm = m0 + ty*4 + i;
        if (gm >= Mm) continue;
#pragma unroll
        for (int j=0;j<4;j++) {
            int gn = n0 + tx*4 + j;
            if (gn >= Nn) continue;
            float v = alpha * acc[i][j];
            long idx = (long)gm*ldc + gn;
            if (ACCUM) Cb[idx] += v; else Cb[idx] = v;
        }
    }
}

// ---------------- small kernels ----------------
__global__ void copy_cls_kernel(const float* __restrict__ c, float* __restrict__ h){
    int i = blockIdx.x*256 + threadIdx.x;
    if (i < DIMF) h[i] = c[i];
}

__global__ void layernorm_kernel(const float* __restrict__ x, const float* __restrict__ w,
                                 const float* __restrict__ b, float* __restrict__ y)
{
    __shared__ float red[256];
    int row = blockIdx.x, tid = threadIdx.x;
    const float* xr = x + (long)row*DIMF;
    float v0 = xr[tid], v1 = xr[tid+256];
    red[tid] = v0+v1; __syncthreads();
    for (int s=128;s;s>>=1){ if(tid<s) red[tid]+=red[tid+s]; __syncthreads(); }
    float m = red[0]*(1.f/512.f); __syncthreads();
    float d0 = v0-m, d1 = v1-m;
    red[tid] = d0*d0+d1*d1; __syncthreads();
    for (int s=128;s;s>>=1){ if(tid<s) red[tid]+=red[tid+s]; __syncthreads(); }
    float rstd = rsqrtf(red[0]*(1.f/512.f) + 1e-5f);
    float* yr = y + (long)row*DIMF;
    yr[tid]     = d0*rstd*w[tid]     + b[tid];
    yr[tid+256] = d1*rstd*w[tid+256] + b[tid+256];
}

__global__ void landmark_kernel(const float* __restrict__ qkv,
                                float* __restrict__ ql, float* __restrict__ kl)
{
    int b = blockIdx.x; int hd = b >> 8; int j = b & 255;
    int d = threadIdx.x;
    float sq = 0.f, sk = 0.f;
    long base = (long)(j*64)*QKV3 + hd*64 + d;
#pragma unroll 4
    for (int i=0;i<64;i++){ sq += qkv[base + (long)i*QKV3]; sk += qkv[base + (long)i*QKV3 + 512]; }
    ql[((hd<<8)+j)*64 + d] = sq*(1.f/64.f);
    kl[((hd<<8)+j)*64 + d] = sk*(1.f/64.f);
}

__global__ void attn2_kernel(const float* __restrict__ ql, const float* __restrict__ kl,
                             float* __restrict__ out)
{
    __shared__ float qrow[64];
    __shared__ float red[256];
    int b = blockIdx.x; int hd = b >> 8; int j = b & 255;
    int tid = threadIdx.x;
    if (tid < 64) qrow[tid] = ql[((hd<<8)+j)*64 + tid];
    __syncthreads();
    const float* krow = kl + ((long)((hd<<8)+tid))*64;
    float acc = 0.f;
#pragma unroll 8
    for (int d=0; d<64; d++) acc += qrow[d]*krow[d];
    red[tid]=acc; __syncthreads();
    for (int s=128;s;s>>=1){ if(tid<s) red[tid]=fmaxf(red[tid],red[tid+s]); __syncthreads(); }
    float mx = red[0]; __syncthreads();
    float e = expf(acc - mx);
    red[tid]=e; __syncthreads();
    for (int s=128;s;s>>=1){ if(tid<s) red[tid]+=red[tid+s]; __syncthreads(); }
    out[((long)((hd<<8)+j))*256 + tid] = e * (1.f/red[0]);
}

__global__ void zero_scal_kernel(float* s){ if (threadIdx.x < 2) s[threadIdx.x] = 0.f; }

__global__ void pinv_max_kernel(const float* __restrict__ x, float* __restrict__ scal)
{
    __shared__ float red[256];
    int b = blockIdx.x, tid = threadIdx.x;
    float s;
    if (b < 2048) { int hd=b>>8, i=b&255; s = x[(((long)(hd<<8)+i)<<8) + tid]; }
    else { int bb=b-2048; int hd=bb>>8, j=bb&255; s = x[(((long)(hd<<8)+tid)<<8) + j]; }
    red[tid]=s; __syncthreads();
    for (int st=128;st;st>>=1){ if(tid<st) red[tid]+=red[tid+st]; __syncthreads(); }
    if (tid==0) atomicMax((int*)&scal[b<2048?0:1], __float_as_int(red[0]));
}

__global__ void zinit_kernel(const float* __restrict__ x, const float* __restrict__ scal,
                             float* __restrict__ z)
{
    int b = blockIdx.x; int hd=b>>8, i=b&255; int j=threadIdx.x;
    float inv = 1.f/(scal[0]*scal[1]);
    z[(((long)(hd<<8)+i)<<8)+j] = x[(((long)(hd<<8)+j)<<8)+i] * inv;
}

__global__ void softmax_stats_kernel(const float* __restrict__ s, int n,
                                     float* __restrict__ m_out, float* __restrict__ rv_out)
{
    __shared__ float red[256];
    long base = (long)blockIdx.x * n;
    int tid = threadIdx.x;
    float mx = -1e30f;
    for (int i=tid;i<n;i+=256) mx = fmaxf(mx, s[base+i]);
    red[tid]=mx; __syncthreads();
    for (int st=128;st;st>>=1){ if(tid<st) red[tid]=fmaxf(red[tid],red[tid+st]); __syncthreads(); }
    mx = red[0]; __syncthreads();
    float sum=0.f;
    for (int i=tid;i<n;i+=256) sum += __expf(s[base+i]-mx);
    red[tid]=sum; __syncthreads();
    for (int st=128;st;st>>=1){ if(tid<st) red[tid]+=red[tid+st]; __syncthreads(); }
    if (tid==0){ m_out[blockIdx.x]=mx; rv_out[blockIdx.x]=1.f/red[0]; }
}

__global__ void reduce_part_kernel(const float* __restrict__ part, float* __restrict__ out,
                                   int chunks, int sz, int nb)
{
    long idx = (long)blockIdx.x*256 + threadIdx.x;
    if (idx >= (long)nb*sz) return;
    int b = (int)(idx / sz); int r = (int)(idx - (long)b*sz);
    float s = 0.f;
    for (int c=0;c<chunks;c++) s += part[((long)(b*chunks+c))*sz + r];
    out[idx] = s;
}

// fused attn1 @ W : 32 tokens x 1 head per block; f32x2 math; in-place into qkv q-slot.
#define KLS_STRIDE 66
__global__ void attn1_kernel(float* __restrict__ qkv, const float* __restrict__ kl,
                             const float* __restrict__ W)
{
    extern __shared__ float sm[];
    float* kls = sm;                       // 256*66
    float* qs  = sm + 256*KLS_STRIDE;      // 32*64
    float* ss  = qs + 32*64;               // 32*256
    int hd = blockIdx.y;
    int i0 = blockIdx.x * 32;
    int tid = threadIdx.x;
    for (int idx = tid; idx < 256*64; idx += 256) {
        int c = idx >> 6, d = idx & 63;
        kls[c*KLS_STRIDE+d] = kl[((long)((hd<<8)+c))*64 + d];
    }
    for (int idx = tid; idx < 32*64; idx += 256) {
        int r = idx >> 6, d = idx & 63;
        qs[idx] = qkv[(long)(i0+r)*QKV3 + hd*64 + d];
    }
    __syncthreads();
    {
        int c = tid;
        const ull* k2 = reinterpret_cast<const ull*>(&kls[c*KLS_STRIDE]);
        for (int r = 0; r < 32; r++) {
            const ull* q2 = reinterpret_cast<const ull*>(&qs[r*64]);
            ull acc2 = 0ull;
#pragma unroll 8
            for (int d2 = 0; d2 < 32; d2++) acc2 = ffma2(q2[d2], k2[d2], acc2);
            float2 p = unpack2(acc2);
            ss[r*256+c] = p.x + p.y;
        }
    }
    __syncthreads();
    {
        int w = tid >> 5, lane = tid & 31;
        for (int r = w*4; r < w*4+4; r++) {
            float mx = -1e30f;
#pragma unroll
            for (int k=0;k<8;k++) mx = fmaxf(mx, ss[r*256 + lane + 32*k]);
            for (int o=16;o;o>>=1) mx = fmaxf(mx, __shfl_xor_sync(0xffffffffu, mx, o));
            float sum = 0.f;
#pragma unroll
            for (int k=0;k<8;k++){ float e = __expf(ss[r*256+lane+32*k]-mx); ss[r*256+lane+32*k]=e; sum+=e; }
            for (int o=16;o;o>>=1) sum += __shfl_xor_sync(0xffffffffu, sum, o);
            float inv = 1.f/sum;
#pragma unroll
            for (int k=0;k<8;k++) ss[r*256+lane+32*k] *= inv;
        }
    }
    __syncthreads();
    {
        int d = tid & 63, rb = tid >> 6;
        ull acc2[8];
#pragma unroll
        for (int j=0;j<8;j++) acc2[j]=0ull;
        const float* Wh = W + (long)hd*ML*DH;
        for (int c2 = 0; c2 < 128; c2++) {
            float w0 = Wh[(2*c2)*64 + d];
            float w1 = Wh[(2*c2+1)*64 + d];
            ull wp = pack2(w0, w1);
#pragma unroll
            for (int j=0;j<8;j++) {
                ull s2 = *reinterpret_cast<const ull*>(&ss[(rb + 4*j)*256 + 2*c2]);
                acc2[j] = ffma2(s2, wp, acc2[j]);
            }
        }
#pragma unroll
        for (int j=0;j<8;j++) {
            float2 p = unpack2(acc2[j]);
            int r = rb + 4*j;
            qkv[(long)(i0+r)*QKV3 + hd*64 + d] = p.x + p.y;
        }
    }
}

// depthwise residual conv over sequence: qkv q-slot += conv(v, res_k)
__global__ void conv_kernel(float* __restrict__ qkv, const float* __restrict__ rk)
{
    __shared__ float rks[NH*33];
    int tid = threadIdx.x;
    for (int i = tid; i < NH*33; i += 256) rks[i] = rk[i];
    __syncthreads();
    long idx = (long)blockIdx.x*256 + tid;
    int i = (int)(idx >> 9); int col = (int)(idx & 511); int hd = col >> 6;
    long addr = (long)i*QKV3 + col;
    float acc = qkv[addr];
#pragma unroll
    for (int t=0;t<33;t++){
        int ii = i + t - 16;
        if (ii >= 0 && ii < N_TOK)
            acc += rks[hd*33+t] * qkv[(long)ii*QKV3 + 1024 + col];
    }
    qkv[addr] = acc;
}

// final: LN on row 0 -> clf -> sigmoid -> cumprod survival
__global__ void final_kernel(const float* __restrict__ h, const float* __restrict__ nw,
                             const float* __restrict__ nb, const float* __restrict__ cw,
                             const float* __restrict__ cb, float* __restrict__ out)
{
    __shared__ float red[512];
    __shared__ float xn[512];
    __shared__ float lg[4];
    int tid = threadIdx.x;
    float v = h[tid];
    red[tid]=v; __syncthreads();
    for (int s=256;s;s>>=1){ if(tid<s) red[tid]+=red[tid+s]; __syncthreads(); }
    float mu = red[0]*(1.f/512.f); __syncthreads();
    float d = v-mu;
    red[tid]=d*d; __syncthreads();
    for (int s=256;s;s>>=1){ if(tid<s) red[tid]+=red[tid+s]; __syncthreads(); }
    float rstd = rsqrtf(red[0]*(1.f/512.f) + 1e-5f);
    xn[tid] = d*rstd*nw[tid] + nb[tid];
    __syncthreads();
    if (tid < 128) {
        int c = tid >> 5, lane = tid & 31;
        float s = 0.f;
        for (int k=lane;k<512;k+=32) s += xn[k]*cw[k*4+c];
        for (int o=16;o;o>>=1) s += __shfl_xor_sync(0xffffffffu, s, o);
        if (lane==0) lg[c] = s + cb[c];
    }
    __syncthreads();
    if (tid==0) {
        float S = 1.f;
        for (int c=0;c<4;c++){
            float hz = 1.f/(1.f+expf(-lg[c]));
            out[c] = hz;
            S *= (1.f - hz);
            out[4+c] = S;
        }
    }
}

// ---------------- host launch ----------------
#define GEMM128P(BI,RE,AC,QS, grid, A,B,bias,C, M,N,K, lda,ldb,ldc, sA,sB,sC) \
    gemm128p_kernel<BI,RE,AC,QS><<<grid, 256>>>(A,B,bias,C,M,N,K,lda,ldb,ldc,(long)(sA),(long)(sB),(long)(sC))

#define GEMM128T(grid, A,B,C, M,N,K, lda,ldb,ldc, sA,sB,sC) \
    gemm128_kernel<true><<<grid, 256>>>(A,B,C,M,N,K,lda,ldb,ldc,(long)(sA),(long)(sB),(long)(sC))

#define GEMM64(TB,AC,DG,EX, grid, A,B,C, mu,rstd, M,N,K, lda,ldb,ldc, sA,sB,sC, kch, al,db,bs) \
    gemm_kernel<TB,AC,DG,EX><<<grid, 256>>>(A,B,C,mu,rstd,M,N,K,lda,ldb,ldc,(long)(sA),(long)(sB),(long)(sC),kch,al,db,bs)

extern "C" void kernel_launch(void* const* d_in, const int* in_sizes, int n_in,
                              void* d_out, int out_size)
{
    const float* x     = (const float*)d_in[0];
    const float* fc_w  = (const float*)d_in[1];
    const float* fc_b  = (const float*)d_in[2];
    const float* cls   = (const float*)d_in[3];
    const float* Lp[2][6];
    for (int l=0;l<2;l++) for (int k=0;k<6;k++) Lp[l][k] = (const float*)d_in[4 + l*6 + k];
    const float* norm_w = (const float*)d_in[16];
    const float* norm_b = (const float*)d_in[17];
    const float* clf_w  = (const float*)d_in[18];
    const float* clf_b  = (const float*)d_in[19];
    float* out = (float*)d_out;
    const float* F0 = 0;

    float *ph,*pqkv,*ps3,*psm,*psrv,*pql,*pkl,*pa2,*pz,*pz2,*pxz,*pt1,*pt2,*ppart,*pa3v,*pW,*pscal;
    cudaGetSymbolAddress((void**)&ph,   g_h);
    cudaGetSymbolAddress((void**)&pqkv, g_qkv);
    cudaGetSymbolAddress((void**)&ps3,  g_s3h);
    cudaGetSymbolAddress((void**)&psm,  g_sm);
    cudaGetSymbolAddress((void**)&psrv, g_srv);
    cudaGetSymbolAddress((void**)&pql,  g_ql);
    cudaGetSymbolAddress((void**)&pkl,  g_kl);
    cudaGetSymbolAddress((void**)&pa2,  g_a2);
    cudaGetSymbolAddress((void**)&pz,   g_z);
    cudaGetSymbolAddress((void**)&pz2,  g_z2);
    cudaGetSymbolAddress((void**)&pxz,  g_xz);
    cudaGetSymbolAddress((void**)&pt1,  g_t1);
    cudaGetSymbolAddress((void**)&pt2,  g_t2b);
    cudaGetSymbolAddress((void**)&ppart,g_part);
    cudaGetSymbolAddress((void**)&pa3v, g_a3v);
    cudaGetSymbolAddress((void**)&pW,   g_W);
    cudaGetSymbolAddress((void**)&pscal,g_scal);

    cudaFuncSetAttribute(attn1_kernel, cudaFuncAttributeMaxDynamicSharedMemorySize, 110592);

    // h[1:] = relu(x @ fc_w + fc_b); h[0] = cls
    GEMM128P(true,true,false,false, dim3(4,128,1),
             x, fc_w, fc_b, ph+DIMF, NX,512,1024, 1024,512,512, 0,0,0);
    copy_cls_kernel<<<2,256>>>(cls, ph);

    for (int l=0;l<2;l++) {
        const float *nw=Lp[l][0], *nb=Lp[l][1], *qw=Lp[l][2],
                    *ow=Lp[l][3], *ob=Lp[l][4], *rk=Lp[l][5];

        // standalone LN into ps3, then pipelined qkv GEMM (q pre-scaled 1/8 in epilogue)
        layernorm_kernel<<<N_TOK,256>>>(ph, nw, nb, ps3);
        GEMM128P(false,false,false,true, dim3(12,128,1),
                 ps3, qw, F0, pqkv, N_TOK,QKV3,512, 512,QKV3,QKV3, 0,0,0);
        landmark_kernel<<<2048,64>>>(pqkv, pql, pkl);
        attn2_kernel<<<2048,256>>>(pql, pkl, pa2);

        // pinv init
        zero_scal_kernel<<<1,32>>>(pscal);
        pinv_max_kernel<<<4096,256>>>(pa2, pscal);
        zinit_kernel<<<2048,256>>>(pa2, pscal, pz);
        float* zc = pz; float* zo = pz2;
        for (int it=0; it<6; it++) {
            GEMM64(false,false,true,false, dim3(4,4,8),
                   pa2, zc, pxz, F0,F0, 256,256,256, 256,256,256, 65536,65536,65536, 1, 1.f,0.f,1.f);
            GEMM64(false,false,true,false, dim3(4,4,8),
                   pxz, pxz, pt1, F0,F0, 256,256,256, 256,256,256, 65536,65536,65536, 1, 1.f,7.f,-1.f);
            GEMM64(false,false,true,false, dim3(4,4,8),
                   pxz, pt1, pt2, F0,F0, 256,256,256, 256,256,256, 65536,65536,65536, 1, 1.f,15.f,-1.f);
            GEMM64(false,false,true,false, dim3(4,4,8),
                   zc, pt2, zo, F0,F0, 256,256,256, 256,256,256, 65536,65536,65536, 1, 0.25f,13.f,-1.f);
            float* tmp=zc; zc=zo; zo=tmp;
        }

        // attn3 @ v, 2 heads per batch; softmax fused into a3v A-load
        for (int h0=0; h0<NH; h0+=2) {
            GEMM128T(dim3(128,2,2),
                     pql + h0*ML*DH, pqkv+512+h0*64, ps3,
                     256,N_TOK,64, 64,QKV3,N_TOK, ML*DH,64,(long)ML*N_TOK);
            softmax_stats_kernel<<<2*ML,256>>>(ps3, N_TOK, psm, psrv);
            GEMM64(false,false,false,true, dim3(1,4,2*32),
                   ps3, pqkv+1024+h0*64, ppart, psm,psrv,
                   256,64,N_TOK, N_TOK,QKV3,64, (long)ML*N_TOK,64,ML*DH, 32, 1.f,0.f,1.f);
            reduce_part_kernel<<<(2*ML*DH+255)/256,256>>>(ppart, pa3v + h0*ML*DH, 32, ML*DH, 2);
        }
        // W = pinv @ a3v  (batched over heads, split-K 4)
        GEMM64(false,false,false,false, dim3(1,4,8*4),
               zc, pa3v, ppart, F0,F0,
               256,64,256, 256,64,64, 65536,ML*DH,ML*DH, 4, 1.f,0.f,1.f);
        reduce_part_kernel<<<(NH*ML*DH+255)/256,256>>>(ppart, pW, 4, ML*DH, NH);

        // fused: q-slot of qkv <- softmax(q @ k_l^T) @ W
        attn1_kernel<<<dim3(512,NH),256,110592>>>(pqkv, pkl, pW);
        // + depthwise residual conv of v
        conv_kernel<<<(N_TOK*DIMF)/256,256>>>(pqkv, rk);
        // h += attn_out @ out_w + out_b
        GEMM128P(true,false,true,false, dim3(4,128,1),
                 pqkv, ow, ob, ph, N_TOK,512,512, 1536,512,512, 0,0,0);
    }

    final_kernel<<<1,512>>>(ph, norm_w, norm_b, clf_w, clf_b, out);
}

// round 13
// speedup vs baseline: 1.9131x; 1.0934x over previous
#include <cuda_runtime.h>
#include <math.h>

// ---------------- problem constants ----------------
#define N_TOK 16384
#define NX    16383
#define DIMF  512
#define NH    8
#define DH    64
#define ML    256      // landmarks
#define QKV3  1536

typedef unsigned long long ull;

// packed f32x2 helpers (sm_103a SIMD fp32)
__device__ __forceinline__ ull ffma2(ull a, ull b, ull c){
    ull d; asm("fma.rn.f32x2 %0,%1,%2,%3;" : "=l"(d) : "l"(a), "l"(b), "l"(c)); return d;
}
__device__ __forceinline__ ull pack2(float x, float y){
    ull d; asm("mov.b64 %0,{%1,%2};" : "=l"(d) : "f"(x), "f"(y)); return d;
}
__device__ __forceinline__ float2 unpack2(ull v){
    float2 r; asm("mov.b64 {%0,%1},%2;" : "=f"(r.x), "=f"(r.y) : "l"(v)); return r;
}

// ---------------- scratch (device globals; ~185 MB total) ----------------
__device__ float g_h   [N_TOK*DIMF];
__device__ float g_qkv [N_TOK*QKV3];        // q|k|v (q slot reused for attn out)
__device__ float g_s3h [2*ML*N_TOK];        // 2-head batched attn3 raw scores
__device__ float g_mu  [N_TOK];
__device__ float g_rstd[N_TOK];
__device__ float g_sm  [2*ML];              // softmax row max
__device__ float g_srv [2*ML];              // softmax row 1/sum
__device__ float g_ql  [NH*ML*DH];
__device__ float g_kl  [NH*ML*DH];
__device__ float g_a2  [NH*ML*ML];
__device__ float g_z   [NH*ML*ML];
__device__ float g_z2  [NH*ML*ML];
__device__ float g_xz  [NH*ML*ML];
__device__ float g_t1  [NH*ML*ML];
__device__ float g_t2b [NH*ML*ML];
__device__ float g_part[64*ML*DH];
__device__ float g_a3v [NH*ML*DH];
__device__ float g_W   [NH*ML*DH];
__device__ float g_scal[2];

// ================= 128x128x16 GEMM, 8x8 microtile, float4 + FFMA2 =================
#define TM 128
#define TN 128
#define TK 16

template<bool TRANSB, bool BIAS, bool RELU, bool ACCUM, bool QSCALE, bool LNA>
__global__ __launch_bounds__(256)
void gemm128_kernel(const float* __restrict__ A, const float* __restrict__ B,
                    const float* __restrict__ bias, float* __restrict__ C,
                    const float* __restrict__ lnw, const float* __restrict__ lnb,
                    const float* __restrict__ mu,  const float* __restrict__ rstd,
                    int Mm, int Nn, int Kk, int lda, int ldb, int ldc,
                    long sA, long sB, long sC)
{
    __shared__ float As[TK][TM+4];
    __shared__ float Bs[TK][TN+4];
    int z = blockIdx.z;
    const float* Ab = A + (long)z * sA;
    const float* Bb = B + (long)z * sB;
    float* Cb = C + (long)z * sC;
    int m0 = blockIdx.y * TM;
    int n0 = blockIdx.x * TN;
    int tid = threadIdx.x;
    int tx = tid & 15, ty = tid >> 4;

    ull acc2[8][4];
#pragma unroll
    for (int i=0;i<8;i++)
#pragma unroll
        for (int j=0;j<4;j++) acc2[i][j]=0ull;

    for (int kt = 0; kt < Kk; kt += TK) {
        // ---- A tile ----
#pragma unroll
        for (int l = 0; l < 2; l++) {
            int i = tid + l*256;
            int m = i >> 2, kq = i & 3;
            int gm = m0 + m, gk = kt + kq*4;
            float4 v = make_float4(0.f,0.f,0.f,0.f);
            if (gm < Mm) {
                v = *reinterpret_cast<const float4*>(&Ab[(long)gm*lda + gk]);
                if (LNA) {
                    float mm = mu[gm], rr = rstd[gm];
                    v.x = (v.x-mm)*rr*lnw[gk+0] + lnb[gk+0];
                    v.y = (v.y-mm)*rr*lnw[gk+1] + lnb[gk+1];
                    v.z = (v.z-mm)*rr*lnw[gk+2] + lnb[gk+2];
                    v.w = (v.w-mm)*rr*lnw[gk+3] + lnb[gk+3];
                }
            }
            As[kq*4+0][m] = v.x;
            As[kq*4+1][m] = v.y;
            As[kq*4+2][m] = v.z;
            As[kq*4+3][m] = v.w;
        }
        // ---- B tile ----
        if (TRANSB) {
#pragma unroll
            for (int l = 0; l < 2; l++) {
                int i = tid + l*256;
                int n = i >> 2, kq = i & 3;
                int gn = n0 + n, gk = kt + kq*4;
                float4 v = *reinterpret_cast<const float4*>(&Bb[(long)gn*ldb + gk]);
                Bs[kq*4+0][n] = v.x;
                Bs[kq*4+1][n] = v.y;
                Bs[kq*4+2][n] = v.z;
                Bs[kq*4+3][n] = v.w;
            }
        } else {
#pragma unroll
            for (int l = 0; l < 2; l++) {
                int i = tid + l*256;
                int kk = i >> 5, nq = i & 31;
                int gn = n0 + nq*4, gk = kt + kk;
                float4 v = *reinterpret_cast<const float4*>(&Bb[(long)gk*ldb + gn]);
                *reinterpret_cast<float4*>(&Bs[kk][nq*4]) = v;
            }
        }
        __syncthreads();
#pragma unroll
        for (int kk = 0; kk < TK; kk++) {
            float4 a0 = *reinterpret_cast<const float4*>(&As[kk][ty*8]);
            float4 a1 = *reinterpret_cast<const float4*>(&As[kk][ty*8+4]);
            const ulonglong2* bp = reinterpret_cast<const ulonglong2*>(&Bs[kk][tx*8]);
            ulonglong2 u0 = bp[0], u1 = bp[1];
            ull b2[4] = {u0.x, u0.y, u1.x, u1.y};
            float a[8] = {a0.x,a0.y,a0.z,a0.w,a1.x,a1.y,a1.z,a1.w};
#pragma unroll
            for (int i=0;i<8;i++) {
                ull ad = pack2(a[i], a[i]);
#pragma unroll
                for (int j=0;j<4;j++) acc2[i][j] = ffma2(ad, b2[j], acc2[i][j]);
            }
        }
        __syncthreads();
    }
    // ---- epilogue ----
#pragma unroll
    for (int i=0;i<8;i++) {
        int gm = m0 + ty*8 + i;
        if (gm >= Mm) continue;
        long rowoff = (long)gm*ldc;
#pragma unroll
        for (int j2=0;j2<4;j2++) {
            float2 p = unpack2(acc2[i][j2]);
            float vv[2] = {p.x, p.y};
#pragma unroll
            for (int s=0;s<2;s++) {
                int gn = n0 + tx*8 + j2*2 + s;
                float v = vv[s];
                if (QSCALE && gn < 512) v *= 0.125f;
                if (BIAS) v += bias[gn];
                if (RELU) v = fmaxf(v, 0.f);
                long idx = rowoff + gn;
                if (ACCUM) Cb[idx] += v; else Cb[idx] = v;
            }
        }
    }
}

// ================= 64x64x16 GEMM (pinv / a3v / W paths) =================
#define BM 64
#define BN 64
#define BK 16

template<bool TRANSB, bool BIAS, bool RELU, bool ACCUM, bool QSCALE, bool DIAGB, bool LNA, bool EXPA>
__global__ __launch_bounds__(256)
void gemm_kernel(const float* __restrict__ A, const float* __restrict__ B,
                 const float* __restrict__ bias, float* __restrict__ C,
                 const float* __restrict__ lnw, const float* __restrict__ lnb,
                 const float* __restrict__ mu,  const float* __restrict__ rstd,
                 int Mm, int Nn, int Kk, int lda, int ldb, int ldc,
                 long sA, long sB, long sC, int kchunks,
                 float alpha, float dbeta, float bsign)
{
    __shared__ float As[BK][BM+1];
    __shared__ float Bs[BK][BN+1];
    int z = blockIdx.z;
    int batch = z / kchunks;
    int chunk = z - batch*kchunks;
    const float* Ab = A + (long)batch * sA;
    const float* Bb = B + (long)batch * sB;
    float* Cb = C + (long)z * sC;
    int kPer   = Kk / kchunks;
    int kstart = chunk * kPer;
    int m0 = blockIdx.y * BM;
    int n0 = blockIdx.x * BN;
    int tid = threadIdx.x;
    int tx = tid & 15, ty = tid >> 4;
    float acc[4][4];
#pragma unroll
    for (int i=0;i<4;i++)
#pragma unroll
        for (int j=0;j<4;j++) acc[i][j]=0.f;

    for (int kt = kstart; kt < kstart + kPer; kt += BK) {
#pragma unroll
        for (int l = 0; l < 4; l++) {
            int i  = tid + l*256;
            int m  = i >> 4, kk = i & 15;
            int gm = m0 + m, gk = kt + kk;
            float v = 0.f;
            if (gm < Mm && gk < Kk) {
                v = Ab[(long)gm*lda + gk];
                if (LNA)  v = (v - mu[gm]) * rstd[gm] * lnw[gk] + lnb[gk];
                if (EXPA) v = __expf(v - mu[(long)batch*Mm + gm]) * rstd[(long)batch*Mm + gm];
            }
            As[kk][m] = v;
        }
#pragma unroll
        for (int l = 0; l < 4; l++) {
            int i = tid + l*256;
            float v; int kk, n;
            if (TRANSB) {
                n = i >> 4; kk = i & 15;
                int gn = n0 + n, gk = kt + kk;
                v = (gn < Nn && gk < Kk) ? Bb[(long)gn*ldb + gk] : 0.f;
            } else {
                kk = i >> 6; n = i & 63;
                int gn = n0 + n, gk = kt + kk;
                v = (gn < Nn && gk < Kk) ? Bb[(long)gk*ldb + gn] : 0.f;
                if (DIAGB) v = dbeta*((gk==gn)?1.f:0.f) + bsign*v;
            }
            Bs[kk][n] = v;
        }
        __syncthreads();
#pragma unroll
        for (int kk = 0; kk < BK; kk++) {
            float a[4], b[4];
#pragma unroll
            for (int i=0;i<4;i++) a[i] = As[kk][ty*4+i];
#pragma unroll
            for (int j=0;j<4;j++) b[j] = Bs[kk][tx*4+j];
#pragma unroll
            for (int i=0;i<4;i++)
#pragma unroll
                for (int j=0;j<4;j++) acc[i][j] += a[i]*b[j];
        }
        __syncthreads();
    }
#pragma unroll
    for (int i=0;i<4;i++) {
        int gm = m0 + ty*4 + i;
        if (gm >= Mm) continue;
#pragma unroll
        for (int j=0;j<4;j++) {
            int gn = n0 + tx*4 + j;
            if (gn >= Nn) continue;
            float v = alpha * acc[i][j];
            if (QSCALE && gn < 512) v *= 0.125f;
            if (BIAS) v += bias[gn];
            if (RELU) v = fmaxf(v, 0.f);
            long idx = (long)gm*ldc + gn;
            if (ACCUM) Cb[idx] += v; else Cb[idx] = v;
        }
    }
}

// ---------------- small kernels ----------------
__global__ void copy_cls_kernel(const float* __restrict__ c, float* __restrict__ h){
    int i = blockIdx.x*256 + threadIdx.x;
    if (i < DIMF) h[i] = c[i];
}

__global__ void ln_stats_kernel(const float* __restrict__ x, float* __restrict__ mu,
                                float* __restrict__ rstd)
{
    __shared__ float red[256];
    int row = blockIdx.x, tid = threadIdx.x;
    const float* xr = x + (long)row*DIMF;
    float v0 = xr[tid], v1 = xr[tid+256];
    red[tid] = v0+v1; __syncthreads();
    for (int s=128;s;s>>=1){ if(tid<s) red[tid]+=red[tid+s]; __syncthreads(); }
    float m = red[0]*(1.f/512.f); __syncthreads();
    float d0 = v0-m, d1 = v1-m;
    red[tid] = d0*d0+d1*d1; __syncthreads();
    for (int s=128;s;s>>=1){ if(tid<s) red[tid]+=red[tid+s]; __syncthreads(); }
    if (tid==0){ mu[row]=m; rstd[row]=rsqrtf(red[0]*(1.f/512.f)+1e-5f); }
}

__global__ void landmark_kernel(const float* __restrict__ qkv,
                                float* __restrict__ ql, float* __restrict__ kl)
{
    int b = blockIdx.x; int hd = b >> 8; int j = b & 255;
    int d = threadIdx.x;
    float sq = 0.f, sk = 0.f;
    long base = (long)(j*64)*QKV3 + hd*64 + d;
#pragma unroll 4
    for (int i=0;i<64;i++){ sq += qkv[base + (long)i*QKV3]; sk += qkv[base + (long)i*QKV3 + 512]; }
    ql[((hd<<8)+j)*64 + d] = sq*(1.f/64.f);
    kl[((hd<<8)+j)*64 + d] = sk*(1.f/64.f);
}

__global__ void attn2_kernel(const float* __restrict__ ql, const float* __restrict__ kl,
                             float* __restrict__ out)
{
    __shared__ float qrow[64];
    __shared__ float red[256];
    int b = blockIdx.x; int hd = b >> 8; int j = b & 255;
    int tid = threadIdx.x;
    if (tid < 64) qrow[tid] = ql[((hd<<8)+j)*64 + tid];
    __syncthreads();
    const float* krow = kl + ((long)((hd<<8)+tid))*64;
    float acc = 0.f;
#pragma unroll 8
    for (int d=0; d<64; d++) acc += qrow[d]*krow[d];
    red[tid]=acc; __syncthreads();
    for (int s=128;s;s>>=1){ if(tid<s) red[tid]=fmaxf(red[tid],red[tid+s]); __syncthreads(); }
    float mx = red[0]; __syncthreads();
    float e = expf(acc - mx);
    red[tid]=e; __syncthreads();
    for (int s=128;s;s>>=1){ if(tid<s) red[tid]+=red[tid+s]; __syncthreads(); }
    out[((long)((hd<<8)+j))*256 + tid] = e * (1.f/red[0]);
}

__global__ void zero_scal_kernel(float* s){ if (threadIdx.x < 2) s[threadIdx.x] = 0.f; }

__global__ void pinv_max_kernel(const float* __restrict__ x, float* __restrict__ scal)
{
    __shared__ float red[256];
    int b = blockIdx.x, tid = threadIdx.x;
    float s;
    if (b < 2048) { int hd=b>>8, i=b&255; s = x[(((long)(hd<<8)+i)<<8) + tid]; }
    else { int bb=b-2048; int hd=bb>>8, j=bb&255; s = x[(((long)(hd<<8)+tid)<<8) + j]; }
    red[tid]=s; __syncthreads();
    for (int st=128;st;st>>=1){ if(tid<st) red[tid]+=red[tid+st]; __syncthreads(); }
    if (tid==0) atomicMax((int*)&scal[b<2048?0:1], __float_as_int(red[0]));
}

__global__ void zinit_kernel(const float* __restrict__ x, const float* __restrict__ scal,
                             float* __restrict__ z)
{
    int b = blockIdx.x; int hd=b>>8, i=b&255; int j=threadIdx.x;
    float inv = 1.f/(scal[0]*scal[1]);
    z[(((long)(hd<<8)+i)<<8)+j] = x[(((long)(hd<<8)+j)<<8)+i] * inv;
}

// softmax row stats only: max + 1/sum(exp(x-max))
__global__ void softmax_stats_kernel(const float* __restrict__ s, int n,
                                     float* __restrict__ m_out, float* __restrict__ rv_out)
{
    __shared__ float red[256];
    long base = (long)blockIdx.x * n;
    int tid = threadIdx.x;
    float mx = -1e30f;
    for (int i=tid;i<n;i+=256) mx = fmaxf(mx, s[base+i]);
    red[tid]=mx; __syncthreads();
    for (int st=128;st;st>>=1){ if(tid<st) red[tid]=fmaxf(red[tid],red[tid+st]); __syncthreads(); }
    mx = red[0]; __syncthreads();
    float sum=0.f;
    for (int i=tid;i<n;i+=256) sum += __expf(s[base+i]-mx);
    red[tid]=sum; __syncthreads();
    for (int st=128;st;st>>=1){ if(tid<st) red[tid]+=red[tid+st]; __syncthreads(); }
    if (tid==0){ m_out[blockIdx.x]=mx; rv_out[blockIdx.x]=1.f/red[0]; }
}

__global__ void reduce_part_kernel(const float* __restrict__ part, float* __restrict__ out,
                                   int chunks, int sz, int nb)
{
    long idx = (long)blockIdx.x*256 + threadIdx.x;
    if (idx >= (long)nb*sz) return;
    int b = (int)(idx / sz); int r = (int)(idx - (long)b*sz);
    float s = 0.f;
    for (int c=0;c<chunks;c++) s += part[((long)(b*chunks+c))*sz + r];
    out[idx] = s;
}

// fused attn1 @ W : 32 tokens x 1 head per block; f32x2 math; in-place into qkv q-slot.
#define KLS_STRIDE 66
__global__ void attn1_kernel(float* __restrict__ qkv, const float* __restrict__ kl,
                             const float* __restrict__ W)
{
    extern __shared__ float sm[];
    float* kls = sm;                       // 256*66
    float* qs  = sm + 256*KLS_STRIDE;      // 32*64
    float* ss  = qs + 32*64;               // 32*256
    int hd = blockIdx.y;
    int i0 = blockIdx.x * 32;
    int tid = threadIdx.x;
    for (int idx = tid; idx < 256*64; idx += 256) {
        int c = idx >> 6, d = idx & 63;
        kls[c*KLS_STRIDE+d] = kl[((long)((hd<<8)+c))*64 + d];
    }
    for (int idx = tid; idx < 32*64; idx += 256) {
        int r = idx >> 6, d = idx & 63;
        qs[idx] = qkv[(long)(i0+r)*QKV3 + hd*64 + d];
    }
    __syncthreads();
    {
        int c = tid;
        const ull* k2 = reinterpret_cast<const ull*>(&kls[c*KLS_STRIDE]);
        for (int r = 0; r < 32; r++) {
            const ull* q2 = reinterpret_cast<const ull*>(&qs[r*64]);
            ull acc2 = 0ull;
#pragma unroll 8
            for (int d2 = 0; d2 < 32; d2++) acc2 = ffma2(q2[d2], k2[d2], acc2);
            float2 p = unpack2(acc2);
            ss[r*256+c] = p.x + p.y;
        }
    }
    __syncthreads();
    {
        int w = tid >> 5, lane = tid & 31;
        for (int r = w*4; r < w*4+4; r++) {
            float mx = -1e30f;
#pragma unroll
            for (int k=0;k<8;k++) mx = fmaxf(mx, ss[r*256 + lane + 32*k]);
            for (int o=16;o;o>>=1) mx = fmaxf(mx, __shfl_xor_sync(0xffffffffu, mx, o));
            float sum = 0.f;
#pragma unroll
            for (int k=0;k<8;k++){ float e = __expf(ss[r*256+lane+32*k]-mx); ss[r*256+lane+32*k]=e; sum+=e; }
            for (int o=16;o;o>>=1) sum += __shfl_xor_sync(0xffffffffu, sum, o);
            float inv = 1.f/sum;
#pragma unroll
            for (int k=0;k<8;k++) ss[r*256+lane+32*k] *= inv;
        }
    }
    __syncthreads();
    {
        int d = tid & 63, rb = tid >> 6;
        ull acc2[8];
#pragma unroll
        for (int j=0;j<8;j++) acc2[j]=0ull;
        const float* Wh = W + (long)hd*ML*DH;
        for (int c2 = 0; c2 < 128; c2++) {
            float w0 = Wh[(2*c2)*64 + d];
            float w1 = Wh[(2*c2+1)*64 + d];
            ull wp = pack2(w0, w1);
#pragma unroll
            for (int j=0;j<8;j++) {
                ull s2 = *reinterpret_cast<const ull*>(&ss[(rb + 4*j)*256 + 2*c2]);
                acc2[j] = ffma2(s2, wp, acc2[j]);
            }
        }
#pragma unroll
        for (int j=0;j<8;j++) {
            float2 p = unpack2(acc2[j]);
            int r = rb + 4*j;
            qkv[(long)(i0+r)*QKV3 + hd*64 + d] = p.x + p.y;
        }
    }
}

// depthwise residual conv over sequence: qkv q-slot += conv(v, res_k)
__global__ void conv_kernel(float* __restrict__ qkv, const float* __restrict__ rk)
{
    __shared__ float rks[NH*33];
    int tid = threadIdx.x;
    for (int i = tid; i < NH*33; i += 256) rks[i] = rk[i];
    __syncthreads();
    long idx = (long)blockIdx.x*256 + tid;
    int i = (int)(idx >> 9); int col = (int)(idx & 511); int hd = col >> 6;
    long addr = (long)i*QKV3 + col;
    float acc = qkv[addr];
#pragma unroll
    for (int t=0;t<33;t++){
        int ii = i + t - 16;
        if (ii >= 0 && ii < N_TOK)
            acc += rks[hd*33+t] * qkv[(long)ii*QKV3 + 1024 + col];
    }
    qkv[addr] = acc;
}

// final: LN on row 0 -> clf -> sigmoid -> cumprod survival
__global__ void final_kernel(const float* __restrict__ h, const float* __restrict__ nw,
                             const float* __restrict__ nb, const float* __restrict__ cw,
                             const float* __restrict__ cb, float* __restrict__ out)
{
    __shared__ float red[512];
    __shared__ float xn[512];
    __shared__ float lg[4];
    int tid = threadIdx.x;
    float v = h[tid];
    red[tid]=v; __syncthreads();
    for (int s=256;s;s>>=1){ if(tid<s) red[tid]+=red[tid+s]; __syncthreads(); }
    float mu = red[0]*(1.f/512.f); __syncthreads();
    float d = v-mu;
    red[tid]=d*d; __syncthreads();
    for (int s=256;s;s>>=1){ if(tid<s) red[tid]+=red[tid+s]; __syncthreads(); }
    float rstd = rsqrtf(red[0]*(1.f/512.f) + 1e-5f);
    xn[tid] = d*rstd*nw[tid] + nb[tid];
    __syncthreads();
    if (tid < 128) {
        int c = tid >> 5, lane = tid & 31;
        float s = 0.f;
        for (int k=lane;k<512;k+=32) s += xn[k]*cw[k*4+c];
        for (int o=16;o;o>>=1) s += __shfl_xor_sync(0xffffffffu, s, o);
        if (lane==0) lg[c] = s + cb[c];
    }
    __syncthreads();
    if (tid==0) {
        float S = 1.f;
        for (int c=0;c<4;c++){
            float hz = 1.f/(1.f+expf(-lg[c]));
            out[c] = hz;
            S *= (1.f - hz);
            out[4+c] = S;
        }
    }
}

// ---------------- host launch ----------------
#define GEMM(TB,BI,RE,AC,QS,DG,LN,EX, grid, st, A,B,bias,C, lnw,lnb,mu,rstd, M,N,K, lda,ldb,ldc, sA,sB,sC, kch, al,db,bs) \
    gemm_kernel<TB,BI,RE,AC,QS,DG,LN,EX><<<grid, 256, 0, st>>>(A,B,bias,C,lnw,lnb,mu,rstd,M,N,K,lda,ldb,ldc,(long)(sA),(long)(sB),(long)(sC),kch,al,db,bs)

#define GEMM128(TB,BI,RE,AC,QS,LN, grid, st, A,B,bias,C, lnw,lnb,mu,rstd, M,N,K, lda,ldb,ldc, sA,sB,sC) \
    gemm128_kernel<TB,BI,RE,AC,QS,LN><<<grid, 256, 0, st>>>(A,B,bias,C,lnw,lnb,mu,rstd,M,N,K,lda,ldb,ldc,(long)(sA),(long)(sB),(long)(sC))

extern "C" void kernel_launch(void* const* d_in, const int* in_sizes, int n_in,
                              void* d_out, int out_size)
{
    const float* x     = (const float*)d_in[0];
    const float* fc_w  = (const float*)d_in[1];
    const float* fc_b  = (const float*)d_in[2];
    const float* cls   = (const float*)d_in[3];
    const float* Lp[2][6];
    for (int l=0;l<2;l++) for (int k=0;k<6;k++) Lp[l][k] = (const float*)d_in[4 + l*6 + k];
    const float* norm_w = (const float*)d_in[16];
    const float* norm_b = (const float*)d_in[17];
    const float* clf_w  = (const float*)d_in[18];
    const float* clf_b  = (const float*)d_in[19];
    float* out = (float*)d_out;
    const float* F0 = 0;

    float *ph,*pqkv,*ps3,*pmu,*prstd,*psm,*psrv,*pql,*pkl,*pa2,*pz,*pz2,*pxz,*pt1,*pt2,*ppart,*pa3v,*pW,*pscal;
    cudaGetSymbolAddress((void**)&ph,   g_h);
    cudaGetSymbolAddress((void**)&pqkv, g_qkv);
    cudaGetSymbolAddress((void**)&ps3,  g_s3h);
    cudaGetSymbolAddress((void**)&pmu,  g_mu);
    cudaGetSymbolAddress((void**)&prstd,g_rstd);
    cudaGetSymbolAddress((void**)&psm,  g_sm);
    cudaGetSymbolAddress((void**)&psrv, g_srv);
    cudaGetSymbolAddress((void**)&pql,  g_ql);
    cudaGetSymbolAddress((void**)&pkl,  g_kl);
    cudaGetSymbolAddress((void**)&pa2,  g_a2);
    cudaGetSymbolAddress((void**)&pz,   g_z);
    cudaGetSymbolAddress((void**)&pz2,  g_z2);
    cudaGetSymbolAddress((void**)&pxz,  g_xz);
    cudaGetSymbolAddress((void**)&pt1,  g_t1);
    cudaGetSymbolAddress((void**)&pt2,  g_t2b);
    cudaGetSymbolAddress((void**)&ppart,g_part);
    cudaGetSymbolAddress((void**)&pa3v, g_a3v);
    cudaGetSymbolAddress((void**)&pW,   g_W);
    cudaGetSymbolAddress((void**)&pscal,g_scal);

    cudaFuncSetAttribute(attn1_kernel, cudaFuncAttributeMaxDynamicSharedMemorySize, 110592);

    // side stream + fork/join events (resource init once; identical GPU work per call)
    static cudaStream_t s2 = 0;
    static cudaEvent_t evF = 0, evJ = 0;
    if (!s2) {
        cudaStreamCreateWithFlags(&s2, cudaStreamNonBlocking);
        cudaEventCreateWithFlags(&evF, cudaEventDisableTiming);
        cudaEventCreateWithFlags(&evJ, cudaEventDisableTiming);
    }
    cudaStream_t s0 = 0;

    // h[1:] = relu(x @ fc_w + fc_b); h[0] = cls
    GEMM128(false,true,true,false,false,false, dim3(4,128,1), s0,
            x, fc_w, fc_b, ph+DIMF, F0,F0,F0,F0, NX,512,1024, 1024,512,512, 0,0,0);
    copy_cls_kernel<<<2,256,0,s0>>>(cls, ph);

    for (int l=0;l<2;l++) {
        const float *nw=Lp[l][0], *nb=Lp[l][1], *qw=Lp[l][2],
                    *ow=Lp[l][3], *ob=Lp[l][4], *rk=Lp[l][5];

        // LN stats + fused-LN qkv GEMM (q pre-scaled by 1/8)
        ln_stats_kernel<<<N_TOK,256,0,s0>>>(ph, pmu, prstd);
        GEMM128(false,false,false,false,true,true, dim3(12,128,1), s0,
                ph, qw, F0, pqkv, nw,nb,pmu,prstd, N_TOK,QKV3,512, 512,QKV3,QKV3, 0,0,0);
        landmark_kernel<<<2048,64,0,s0>>>(pqkv, pql, pkl);
        attn2_kernel<<<2048,256,0,s0>>>(pql, pkl, pa2);

        // ---- fork: pinv chain on s2, attn3 chain on s0 ----
        cudaEventRecord(evF, s0);
        cudaStreamWaitEvent(s2, evF, 0);

        // pinv chain (s2)
        zero_scal_kernel<<<1,32,0,s2>>>(pscal);
        pinv_max_kernel<<<4096,256,0,s2>>>(pa2, pscal);
        zinit_kernel<<<2048,256,0,s2>>>(pa2, pscal, pz);
        float* zc = pz; float* zo = pz2;
        for (int it=0; it<6; it++) {
            GEMM(false,false,false,false,false,true,false,false, dim3(4,4,8), s2,
                 pa2, zc, F0, pxz, F0,F0,F0,F0, 256,256,256, 256,256,256, 65536,65536,65536, 1, 1.f,0.f,1.f);
            GEMM(false,false,false,false,false,true,false,false, dim3(4,4,8), s2,
                 pxz, pxz, F0, pt1, F0,F0,F0,F0, 256,256,256, 256,256,256, 65536,65536,65536, 1, 1.f,7.f,-1.f);
            GEMM(false,false,false,false,false,true,false,false, dim3(4,4,8), s2,
                 pxz, pt1, F0, pt2, F0,F0,F0,F0, 256,256,256, 256,256,256, 65536,65536,65536, 1, 1.f,15.f,-1.f);
            GEMM(false,false,false,false,false,true,false,false, dim3(4,4,8), s2,
                 zc, pt2, F0, zo, F0,F0,F0,F0, 256,256,256, 256,256,256, 65536,65536,65536, 1, 0.25f,13.f,-1.f);
            float* tmp=zc; zc=zo; zo=tmp;
        }

        // attn3 chain (s0): 2 heads per batch; softmax fused into a3v A-load
        for (int h0=0; h0<NH; h0+=2) {
            GEMM128(true,false,false,false,false,false, dim3(128,2,2), s0,
                    pql + h0*ML*DH, pqkv+512+h0*64, F0, ps3, F0,F0,F0,F0,
                    256,N_TOK,64, 64,QKV3,N_TOK, ML*DH,64,(long)ML*N_TOK);
            softmax_stats_kernel<<<2*ML,256,0,s0>>>(ps3, N_TOK, psm, psrv);
            GEMM(false,false,false,false,false,false,false,true, dim3(1,4,2*32), s0,
                 ps3, pqkv+1024+h0*64, F0, ppart, F0,F0,psm,psrv,
                 256,64,N_TOK, N_TOK,QKV3,64, (long)ML*N_TOK,64,ML*DH, 32, 1.f,0.f,1.f);
            reduce_part_kernel<<<(2*ML*DH+255)/256,256,0,s0>>>(ppart, pa3v + h0*ML*DH, 32, ML*DH, 2);
        }

        // ---- join ----
        cudaEventRecord(evJ, s2);
        cudaStreamWaitEvent(s0, evJ, 0);

        // W = pinv @ a3v  (batched over heads, split-K 4)
        GEMM(false,false,false,false,false,false,false,false, dim3(1,4,8*4), s0,
             zc, pa3v, F0, ppart, F0,F0,F0,F0,
             256,64,256, 256,64,64, 65536,ML*DH,ML*DH, 4, 1.f,0.f,1.f);
        reduce_part_kernel<<<(NH*ML*DH+255)/256,256,0,s0>>>(ppart, pW, 4, ML*DH, NH);

        // fused: q-slot of qkv <- softmax(q @ k_l^T) @ W
        attn1_kernel<<<dim3(512,NH),256,110592,s0>>>(pqkv, pkl, pW);
        // + depthwise residual conv of v
        conv_kernel<<<(N_TOK*DIMF)/256,256,0,s0>>>(pqkv, rk);
        // h += attn_out @ out_w + out_b
        GEMM128(false,true,false,true,false,false, dim3(4,128,1), s0,
                pqkv, ow, ob, ph, F0,F0,F0,F0, N_TOK,512,512, 1536,512,512, 0,0,0);
    }

    final_kernel<<<1,512,0,s0>>>(ph, norm_w, norm_b, clf_w, clf_b, out);
}

// round 14
// speedup vs baseline: 2.5002x; 1.3069x over previous
#include <cuda_runtime.h>
#include <math.h>

// ---------------- problem constants ----------------
#define N_TOK 16384
#define NX    16383
#define DIMF  512
#define NH    8
#define DH    64
#define ML    256      // landmarks
#define QKV3  1536

typedef unsigned long long ull;

// packed f32x2 helpers (sm_103a SIMD fp32)
__device__ __forceinline__ ull ffma2(ull a, ull b, ull c){
    ull d; asm("fma.rn.f32x2 %0,%1,%2,%3;" : "=l"(d) : "l"(a), "l"(b), "l"(c)); return d;
}
__device__ __forceinline__ ull pack2(float x, float y){
    ull d; asm("mov.b64 %0,{%1,%2};" : "=l"(d) : "f"(x), "f"(y)); return d;
}
__device__ __forceinline__ float2 unpack2(ull v){
    float2 r; asm("mov.b64 {%0,%1},%2;" : "=f"(r.x), "=f"(r.y) : "l"(v)); return r;
}
// tf32 helpers
__device__ __forceinline__ unsigned f2tf(float x){
    unsigned r; asm("cvt.rna.tf32.f32 %0, %1;" : "=r"(r) : "f"(x)); return r;
}
__device__ __forceinline__ void mma_tf32(float* c, const unsigned* a, const unsigned* b){
    asm volatile("mma.sync.aligned.m16n8k8.row.col.f32.tf32.tf32.f32 "
        "{%0,%1,%2,%3}, {%4,%5,%6,%7}, {%8,%9}, {%0,%1,%2,%3};"
        : "+f"(c[0]), "+f"(c[1]), "+f"(c[2]), "+f"(c[3])
        : "r"(a[0]), "r"(a[1]), "r"(a[2]), "r"(a[3]), "r"(b[0]), "r"(b[1]));
}

// ---------------- scratch (device globals; ~185 MB total) ----------------
__device__ float g_h   [N_TOK*DIMF];
__device__ float g_qkv [N_TOK*QKV3];        // q|k|v (q slot reused for attn out)
__device__ float g_s3h [2*ML*N_TOK];        // 2-head batched attn3 raw scores
__device__ float g_mu  [N_TOK];
__device__ float g_rstd[N_TOK];
__device__ float g_sm  [2*ML];              // softmax row max
__device__ float g_srv [2*ML];              // softmax row 1/sum
__device__ float g_ql  [NH*ML*DH];
__device__ float g_kl  [NH*ML*DH];
__device__ float g_a2  [NH*ML*ML];
__device__ float g_z   [NH*ML*ML];
__device__ float g_z2  [NH*ML*ML];
__device__ float g_xz  [NH*ML*ML];
__device__ float g_t1  [NH*ML*ML];
__device__ float g_t2b [NH*ML*ML];
__device__ float g_part[64*ML*DH];
__device__ float g_a3v [NH*ML*DH];
__device__ float g_W   [NH*ML*DH];
__device__ float g_scal[2];

// ====== 128x128x16 GEMM via tf32 mma.sync (tensor pipe), 8 warps 64x32 tiles ======
#define TM 128
#define TN 128
#define TK 16
#define SMS 136   // smem row stride (conflict-free fragment loads: 136%32 == 8)

template<bool TRANSB, bool BIAS, bool RELU, bool ACCUM, bool QSCALE, bool LNA>
__global__ __launch_bounds__(256)
void gemm128_kernel(const float* __restrict__ A, const float* __restrict__ B,
                    const float* __restrict__ bias, float* __restrict__ C,
                    const float* __restrict__ lnw, const float* __restrict__ lnb,
                    const float* __restrict__ mu,  const float* __restrict__ rstd,
                    int Mm, int Nn, int Kk, int lda, int ldb, int ldc,
                    long sA, long sB, long sC)
{
    __shared__ float As[TK][SMS];
    __shared__ float Bs[TK][SMS];
    int z = blockIdx.z;
    const float* Ab = A + (long)z * sA;
    const float* Bb = B + (long)z * sB;
    float* Cb = C + (long)z * sC;
    int m0 = blockIdx.y * TM;
    int n0 = blockIdx.x * TN;
    int tid = threadIdx.x;
    int lane = tid & 31, warp = tid >> 5;
    int wm = warp & 1, wn = warp >> 1;       // warp tile: 64m x 32n
    int row = lane >> 2, tg = lane & 3;

    float acc[4][4][4];
#pragma unroll
    for (int mt=0;mt<4;mt++)
#pragma unroll
        for (int nt=0;nt<4;nt++)
#pragma unroll
            for (int f=0;f<4;f++) acc[mt][nt][f]=0.f;

    for (int kt = 0; kt < Kk; kt += TK) {
        // ---- A tile: 128 rows x 16 k ----
#pragma unroll
        for (int l = 0; l < 2; l++) {
            int i = tid + l*256;
            int m = i >> 2, kq = i & 3;
            int gm = m0 + m, gk = kt + kq*4;
            float4 v = make_float4(0.f,0.f,0.f,0.f);
            if (gm < Mm) {
                v = *reinterpret_cast<const float4*>(&Ab[(long)gm*lda + gk]);
                if (LNA) {
                    float mm = mu[gm], rr = rstd[gm];
                    v.x = (v.x-mm)*rr*lnw[gk+0] + lnb[gk+0];
                    v.y = (v.y-mm)*rr*lnw[gk+1] + lnb[gk+1];
                    v.z = (v.z-mm)*rr*lnw[gk+2] + lnb[gk+2];
                    v.w = (v.w-mm)*rr*lnw[gk+3] + lnb[gk+3];
                }
            }
            As[kq*4+0][m] = v.x;
            As[kq*4+1][m] = v.y;
            As[kq*4+2][m] = v.z;
            As[kq*4+3][m] = v.w;
        }
        // ---- B tile ----
        if (TRANSB) {
#pragma unroll
            for (int l = 0; l < 2; l++) {
                int i = tid + l*256;
                int n = i >> 2, kq = i & 3;
                int gn = n0 + n, gk = kt + kq*4;
                float4 v = *reinterpret_cast<const float4*>(&Bb[(long)gn*ldb + gk]);
                Bs[kq*4+0][n] = v.x;
                Bs[kq*4+1][n] = v.y;
                Bs[kq*4+2][n] = v.z;
                Bs[kq*4+3][n] = v.w;
            }
        } else {
#pragma unroll
            for (int l = 0; l < 2; l++) {
                int i = tid + l*256;
                int kk = i >> 5, nq = i & 31;
                int gn = n0 + nq*4, gk = kt + kk;
                float4 v = *reinterpret_cast<const float4*>(&Bb[(long)gk*ldb + gn]);
                *reinterpret_cast<float4*>(&Bs[kk][nq*4]) = v;
            }
        }
        __syncthreads();
        // ---- two k8 MMA steps ----
#pragma unroll
        for (int ks = 0; ks < 2; ks++) {
            int k0 = ks*8;
            unsigned afr[4][4], bfr[4][2];
#pragma unroll
            for (int mt=0;mt<4;mt++){
                int mb = wm*64 + mt*16;
                afr[mt][0] = f2tf(As[k0+tg  ][mb+row]);
                afr[mt][1] = f2tf(As[k0+tg  ][mb+row+8]);
                afr[mt][2] = f2tf(As[k0+tg+4][mb+row]);
                afr[mt][3] = f2tf(As[k0+tg+4][mb+row+8]);
            }
#pragma unroll
            for (int nt=0;nt<4;nt++){
                int nb = wn*32 + nt*8;
                bfr[nt][0] = f2tf(Bs[k0+tg  ][nb+row]);
                bfr[nt][1] = f2tf(Bs[k0+tg+4][nb+row]);
            }
#pragma unroll
            for (int mt=0;mt<4;mt++)
#pragma unroll
                for (int nt=0;nt<4;nt++)
                    mma_tf32(acc[mt][nt], afr[mt], bfr[nt]);
        }
        __syncthreads();
    }
    // ---- epilogue ----
#pragma unroll
    for (int mt=0;mt<4;mt++){
#pragma unroll
        for (int half=0; half<2; half++){
            int gm = m0 + wm*64 + mt*16 + row + half*8;
            if (gm >= Mm) continue;
            long rowoff = (long)gm*ldc;
#pragma unroll
            for (int nt=0;nt<4;nt++){
                int gn = n0 + wn*32 + nt*8 + 2*tg;
                float v0 = acc[mt][nt][half*2+0];
                float v1 = acc[mt][nt][half*2+1];
                if (QSCALE) { if (gn < 512) v0 *= 0.125f; if (gn+1 < 512) v1 *= 0.125f; }
                if (BIAS)   { v0 += bias[gn]; v1 += bias[gn+1]; }
                if (RELU)   { v0 = fmaxf(v0,0.f); v1 = fmaxf(v1,0.f); }
                if (ACCUM)  { Cb[rowoff+gn] += v0; Cb[rowoff+gn+1] += v1; }
                else        { Cb[rowoff+gn]  = v0; Cb[rowoff+gn+1]  = v1; }
            }
        }
    }
}

// ================= 64x64x16 GEMM (pinv / a3v / W paths) =================
#define BM 64
#define BN 64
#define BK 16

template<bool TRANSB, bool BIAS, bool RELU, bool ACCUM, bool QSCALE, bool DIAGB, bool LNA, bool EXPA>
__global__ __launch_bounds__(256)
void gemm_kernel(const float* __restrict__ A, const float* __restrict__ B,
                 const float* __restrict__ bias, float* __restrict__ C,
                 const float* __restrict__ lnw, const float* __restrict__ lnb,
                 const float* __restrict__ mu,  const float* __restrict__ rstd,
                 int Mm, int Nn, int Kk, int lda, int ldb, int ldc,
                 long sA, long sB, long sC, int kchunks,
                 float alpha, float dbeta, float bsign)
{
    __shared__ float As[BK][BM+1];
    __shared__ float Bs[BK][BN+1];
    int z = blockIdx.z;
    int batch = z / kchunks;
    int chunk = z - batch*kchunks;
    const float* Ab = A + (long)batch * sA;
    const float* Bb = B + (long)batch * sB;
    float* Cb = C + (long)z * sC;
    int kPer   = Kk / kchunks;
    int kstart = chunk * kPer;
    int m0 = blockIdx.y * BM;
    int n0 = blockIdx.x * BN;
    int tid = threadIdx.x;
    int tx = tid & 15, ty = tid >> 4;
    float acc[4][4];
#pragma unroll
    for (int i=0;i<4;i++)
#pragma unroll
        for (int j=0;j<4;j++) acc[i][j]=0.f;

    for (int kt = kstart; kt < kstart + kPer; kt += BK) {
#pragma unroll
        for (int l = 0; l < 4; l++) {
            int i  = tid + l*256;
            int m  = i >> 4, kk = i & 15;
            int gm = m0 + m, gk = kt + kk;
            float v = 0.f;
            if (gm < Mm && gk < Kk) {
                v = Ab[(long)gm*lda + gk];
                if (LNA)  v = (v - mu[gm]) * rstd[gm] * lnw[gk] + lnb[gk];
                if (EXPA) v = __expf(v - mu[(long)batch*Mm + gm]) * rstd[(long)batch*Mm + gm];
            }
            As[kk][m] = v;
        }
#pragma unroll
        for (int l = 0; l < 4; l++) {
            int i = tid + l*256;
            float v; int kk, n;
            if (TRANSB) {
                n = i >> 4; kk = i & 15;
                int gn = n0 + n, gk = kt + kk;
                v = (gn < Nn && gk < Kk) ? Bb[(long)gn*ldb + gk] : 0.f;
            } else {
                kk = i >> 6; n = i & 63;
                int gn = n0 + n, gk = kt + kk;
                v = (gn < Nn && gk < Kk) ? Bb[(long)gk*ldb + gn] : 0.f;
                if (DIAGB) v = dbeta*((gk==gn)?1.f:0.f) + bsign*v;
            }
            Bs[kk][n] = v;
        }
        __syncthreads();
#pragma unroll
        for (int kk = 0; kk < BK; kk++) {
            float a[4], b[4];
#pragma unroll
            for (int i=0;i<4;i++) a[i] = As[kk][ty*4+i];
#pragma unroll
            for (int j=0;j<4;j++) b[j] = Bs[kk][tx*4+j];
#pragma unroll
            for (int i=0;i<4;i++)
#pragma unroll
                for (int j=0;j<4;j++) acc[i][j] += a[i]*b[j];
        }
        __syncthreads();
    }
#pragma unroll
    for (int i=0;i<4;i++) {
        int gm = m0 + ty*4 + i;
        if (gm >= Mm) continue;
#pragma unroll
        for (int j=0;j<4;j++) {
            int gn = n0 + tx*4 + j;
            if (gn >= Nn) continue;
            float v = alpha * acc[i][j];
            if (QSCALE && gn < 512) v *= 0.125f;
            if (BIAS) v += bias[gn];
            if (RELU) v = fmaxf(v, 0.f);
            long idx = (long)gm*ldc + gn;
            if (ACCUM) Cb[idx] += v; else Cb[idx] = v;
        }
    }
}

// ---------------- small kernels ----------------
__global__ void copy_cls_kernel(const float* __restrict__ c, float* __restrict__ h){
    int i = blockIdx.x*256 + threadIdx.x;
    if (i < DIMF) h[i] = c[i];
}

__global__ void ln_stats_kernel(const float* __restrict__ x, float* __restrict__ mu,
                                float* __restrict__ rstd)
{
    __shared__ float red[256];
    int row = blockIdx.x, tid = threadIdx.x;
    const float* xr = x + (long)row*DIMF;
    float v0 = xr[tid], v1 = xr[tid+256];
    red[tid] = v0+v1; __syncthreads();
    for (int s=128;s;s>>=1){ if(tid<s) red[tid]+=red[tid+s]; __syncthreads(); }
    float m = red[0]*(1.f/512.f); __syncthreads();
    float d0 = v0-m, d1 = v1-m;
    red[tid] = d0*d0+d1*d1; __syncthreads();
    for (int s=128;s;s>>=1){ if(tid<s) red[tid]+=red[tid+s]; __syncthreads(); }
    if (tid==0){ mu[row]=m; rstd[row]=rsqrtf(red[0]*(1.f/512.f)+1e-5f); }
}

__global__ void landmark_kernel(const float* __restrict__ qkv,
                                float* __restrict__ ql, float* __restrict__ kl)
{
    int b = blockIdx.x; int hd = b >> 8; int j = b & 255;
    int d = threadIdx.x;
    float sq = 0.f, sk = 0.f;
    long base = (long)(j*64)*QKV3 + hd*64 + d;
#pragma unroll 4
    for (int i=0;i<64;i++){ sq += qkv[base + (long)i*QKV3]; sk += qkv[base + (long)i*QKV3 + 512]; }
    ql[((hd<<8)+j)*64 + d] = sq*(1.f/64.f);
    kl[((hd<<8)+j)*64 + d] = sk*(1.f/64.f);
}

__global__ void attn2_kernel(const float* __restrict__ ql, const float* __restrict__ kl,
                             float* __restrict__ out)
{
    __shared__ float qrow[64];
    __shared__ float red[256];
    int b = blockIdx.x; int hd = b >> 8; int j = b & 255;
    int tid = threadIdx.x;
    if (tid < 64) qrow[tid] = ql[((hd<<8)+j)*64 + tid];
    __syncthreads();
    const float* krow = kl + ((long)((hd<<8)+tid))*64;
    float acc = 0.f;
#pragma unroll 8
    for (int d=0; d<64; d++) acc += qrow[d]*krow[d];
    red[tid]=acc; __syncthreads();
    for (int s=128;s;s>>=1){ if(tid<s) red[tid]=fmaxf(red[tid],red[tid+s]); __syncthreads(); }
    float mx = red[0]; __syncthreads();
    float e = expf(acc - mx);
    red[tid]=e; __syncthreads();
    for (int s=128;s;s>>=1){ if(tid<s) red[tid]+=red[tid+s]; __syncthreads(); }
    out[((long)((hd<<8)+j))*256 + tid] = e * (1.f/red[0]);
}

__global__ void zero_scal_kernel(float* s){ if (threadIdx.x < 2) s[threadIdx.x] = 0.f; }

__global__ void pinv_max_kernel(const float* __restrict__ x, float* __restrict__ scal)
{
    __shared__ float red[256];
    int b = blockIdx.x, tid = threadIdx.x;
    float s;
    if (b < 2048) { int hd=b>>8, i=b&255; s = x[(((long)(hd<<8)+i)<<8) + tid]; }
    else { int bb=b-2048; int hd=bb>>8, j=bb&255; s = x[(((long)(hd<<8)+tid)<<8) + j]; }
    red[tid]=s; __syncthreads();
    for (int st=128;st;st>>=1){ if(tid<st) red[tid]+=red[tid+st]; __syncthreads(); }
    if (tid==0) atomicMax((int*)&scal[b<2048?0:1], __float_as_int(red[0]));
}

__global__ void zinit_kernel(const float* __restrict__ x, const float* __restrict__ scal,
                             float* __restrict__ z)
{
    int b = blockIdx.x; int hd=b>>8, i=b&255; int j=threadIdx.x;
    float inv = 1.f/(scal[0]*scal[1]);
    z[(((long)(hd<<8)+i)<<8)+j] = x[(((long)(hd<<8)+j)<<8)+i] * inv;
}

// softmax row stats only: max + 1/sum(exp(x-max))
__global__ void softmax_stats_kernel(const float* __restrict__ s, int n,
                                     float* __restrict__ m_out, float* __restrict__ rv_out)
{
    __shared__ float red[256];
    long base = (long)blockIdx.x * n;
    int tid = threadIdx.x;
    float mx = -1e30f;
    for (int i=tid;i<n;i+=256) mx = fmaxf(mx, s[base+i]);
    red[tid]=mx; __syncthreads();
    for (int st=128;st;st>>=1){ if(tid<st) red[tid]=fmaxf(red[tid],red[tid+st]); __syncthreads(); }
    mx = red[0]; __syncthreads();
    float sum=0.f;
    for (int i=tid;i<n;i+=256) sum += __expf(s[base+i]-mx);
    red[tid]=sum; __syncthreads();
    for (int st=128;st;st>>=1){ if(tid<st) red[tid]+=red[tid+st]; __syncthreads(); }
    if (tid==0){ m_out[blockIdx.x]=mx; rv_out[blockIdx.x]=1.f/red[0]; }
}

__global__ void reduce_part_kernel(const float* __restrict__ part, float* __restrict__ out,
                                   int chunks, int sz, int nb)
{
    long idx = (long)blockIdx.x*256 + threadIdx.x;
    if (idx >= (long)nb*sz) return;
    int b = (int)(idx / sz); int r = (int)(idx - (long)b*sz);
    float s = 0.f;
    for (int c=0;c<chunks;c++) s += part[((long)(b*chunks+c))*sz + r];
    out[idx] = s;
}

// fused attn1 @ W : 32 tokens x 1 head per block; f32x2 math; in-place into qkv q-slot.
#define KLS_STRIDE 66
__global__ void attn1_kernel(float* __restrict__ qkv, const float* __restrict__ kl,
                             const float* __restrict__ W)
{
    extern __shared__ float sm[];
    float* kls = sm;                       // 256*66
    float* qs  = sm + 256*KLS_STRIDE;      // 32*64
    float* ss  = qs + 32*64;               // 32*256
    int hd = blockIdx.y;
    int i0 = blockIdx.x * 32;
    int tid = threadIdx.x;
    for (int idx = tid; idx < 256*64; idx += 256) {
        int c = idx >> 6, d = idx & 63;
        kls[c*KLS_STRIDE+d] = kl[((long)((hd<<8)+c))*64 + d];
    }
    for (int idx = tid; idx < 32*64; idx += 256) {
        int r = idx >> 6, d = idx & 63;
        qs[idx] = qkv[(long)(i0+r)*QKV3 + hd*64 + d];
    }
    __syncthreads();
    {
        int c = tid;
        const ull* k2 = reinterpret_cast<const ull*>(&kls[c*KLS_STRIDE]);
        for (int r = 0; r < 32; r++) {
            const ull* q2 = reinterpret_cast<const ull*>(&qs[r*64]);
            ull acc2 = 0ull;
#pragma unroll 8
            for (int d2 = 0; d2 < 32; d2++) acc2 = ffma2(q2[d2], k2[d2], acc2);
            float2 p = unpack2(acc2);
            ss[r*256+c] = p.x + p.y;
        }
    }
    __syncthreads();
    {
        int w = tid >> 5, lane = tid & 31;
        for (int r = w*4; r < w*4+4; r++) {
            float mx = -1e30f;
#pragma unroll
            for (int k=0;k<8;k++) mx = fmaxf(mx, ss[r*256 + lane + 32*k]);
            for (int o=16;o;o>>=1) mx = fmaxf(mx, __shfl_xor_sync(0xffffffffu, mx, o));
            float sum = 0.f;
#pragma unroll
            for (int k=0;k<8;k++){ float e = __expf(ss[r*256+lane+32*k]-mx); ss[r*256+lane+32*k]=e; sum+=e; }
            for (int o=16;o;o>>=1) sum += __shfl_xor_sync(0xffffffffu, sum, o);
            float inv = 1.f/sum;
#pragma unroll
            for (int k=0;k<8;k++) ss[r*256+lane+32*k] *= inv;
        }
    }
    __syncthreads();
    {
        int d = tid & 63, rb = tid >> 6;
        ull acc2[8];
#pragma unroll
        for (int j=0;j<8;j++) acc2[j]=0ull;
        const float* Wh = W + (long)hd*ML*DH;
        for (int c2 = 0; c2 < 128; c2++) {
            float w0 = Wh[(2*c2)*64 + d];
            float w1 = Wh[(2*c2+1)*64 + d];
            ull wp = pack2(w0, w1);
#pragma unroll
            for (int j=0;j<8;j++) {
                ull s2 = *reinterpret_cast<const ull*>(&ss[(rb + 4*j)*256 + 2*c2]);
                acc2[j] = ffma2(s2, wp, acc2[j]);
            }
        }
#pragma unroll
        for (int j=0;j<8;j++) {
            float2 p = unpack2(acc2[j]);
            int r = rb + 4*j;
            qkv[(long)(i0+r)*QKV3 + hd*64 + d] = p.x + p.y;
        }
    }
}

// depthwise residual conv over sequence: qkv q-slot += conv(v, res_k)
__global__ void conv_kernel(float* __restrict__ qkv, const float* __restrict__ rk)
{
    __shared__ float rks[NH*33];
    int tid = threadIdx.x;
    for (int i = tid; i < NH*33; i += 256) rks[i] = rk[i];
    __syncthreads();
    long idx = (long)blockIdx.x*256 + tid;
    int i = (int)(idx >> 9); int col = (int)(idx & 511); int hd = col >> 6;
    long addr = (long)i*QKV3 + col;
    float acc = qkv[addr];
#pragma unroll
    for (int t=0;t<33;t++){
        int ii = i + t - 16;
        if (ii >= 0 && ii < N_TOK)
            acc += rks[hd*33+t] * qkv[(long)ii*QKV3 + 1024 + col];
    }
    qkv[addr] = acc;
}

// final: LN on row 0 -> clf -> sigmoid -> cumprod survival
__global__ void final_kernel(const float* __restrict__ h, const float* __restrict__ nw,
                             const float* __restrict__ nb, const float* __restrict__ cw,
                             const float* __restrict__ cb, float* __restrict__ out)
{
    __shared__ float red[512];
    __shared__ float xn[512];
    __shared__ float lg[4];
    int tid = threadIdx.x;
    float v = h[tid];
    red[tid]=v; __syncthreads();
    for (int s=256;s;s>>=1){ if(tid<s) red[tid]+=red[tid+s]; __syncthreads(); }
    float mu = red[0]*(1.f/512.f); __syncthreads();
    float d = v-mu;
    red[tid]=d*d; __syncthreads();
    for (int s=256;s;s>>=1){ if(tid<s) red[tid]+=red[tid+s]; __syncthreads(); }
    float rstd = rsqrtf(red[0]*(1.f/512.f) + 1e-5f);
    xn[tid] = d*rstd*nw[tid] + nb[tid];
    __syncthreads();
    if (tid < 128) {
        int c = tid >> 5, lane = tid & 31;
        float s = 0.f;
        for (int k=lane;k<512;k+=32) s += xn[k]*cw[k*4+c];
        for (int o=16;o;o>>=1) s += __shfl_xor_sync(0xffffffffu, s, o);
        if (lane==0) lg[c] = s + cb[c];
    }
    __syncthreads();
    if (tid==0) {
        float S = 1.f;
        for (int c=0;c<4;c++){
            float hz = 1.f/(1.f+expf(-lg[c]));
            out[c] = hz;
            S *= (1.f - hz);
            out[4+c] = S;
        }
    }
}

// ---------------- host launch ----------------
#define GEMM(TB,BI,RE,AC,QS,DG,LN,EX, grid, st, A,B,bias,C, lnw,lnb,mu,rstd, M,N,K, lda,ldb,ldc, sA,sB,sC, kch, al,db,bs) \
    gemm_kernel<TB,BI,RE,AC,QS,DG,LN,EX><<<grid, 256, 0, st>>>(A,B,bias,C,lnw,lnb,mu,rstd,M,N,K,lda,ldb,ldc,(long)(sA),(long)(sB),(long)(sC),kch,al,db,bs)

#define GEMM128(TB,BI,RE,AC,QS,LN, grid, st, A,B,bias,C, lnw,lnb,mu,rstd, M,N,K, lda,ldb,ldc, sA,sB,sC) \
    gemm128_kernel<TB,BI,RE,AC,QS,LN><<<grid, 256, 0, st>>>(A,B,bias,C,lnw,lnb,mu,rstd,M,N,K,lda,ldb,ldc,(long)(sA),(long)(sB),(long)(sC))

extern "C" void kernel_launch(void* const* d_in, const int* in_sizes, int n_in,
                              void* d_out, int out_size)
{
    const float* x     = (const float*)d_in[0];
    const float* fc_w  = (const float*)d_in[1];
    const float* fc_b  = (const float*)d_in[2];
    const float* cls   = (const float*)d_in[3];
    const float* Lp[2][6];
    for (int l=0;l<2;l++) for (int k=0;k<6;k++) Lp[l][k] = (const float*)d_in[4 + l*6 + k];
    const float* norm_w = (const float*)d_in[16];
    const float* norm_b = (const float*)d_in[17];
    const float* clf_w  = (const float*)d_in[18];
    const float* clf_b  = (const float*)d_in[19];
    float* out = (float*)d_out;
    const float* F0 = 0;

    float *ph,*pqkv,*ps3,*pmu,*prstd,*psm,*psrv,*pql,*pkl,*pa2,*pz,*pz2,*pxz,*pt1,*pt2,*ppart,*pa3v,*pW,*pscal;
    cudaGetSymbolAddress((void**)&ph,   g_h);
    cudaGetSymbolAddress((void**)&pqkv, g_qkv);
    cudaGetSymbolAddress((void**)&ps3,  g_s3h);
    cudaGetSymbolAddress((void**)&pmu,  g_mu);
    cudaGetSymbolAddress((void**)&prstd,g_rstd);
    cudaGetSymbolAddress((void**)&psm,  g_sm);
    cudaGetSymbolAddress((void**)&psrv, g_srv);
    cudaGetSymbolAddress((void**)&pql,  g_ql);
    cudaGetSymbolAddress((void**)&pkl,  g_kl);
    cudaGetSymbolAddress((void**)&pa2,  g_a2);
    cudaGetSymbolAddress((void**)&pz,   g_z);
    cudaGetSymbolAddress((void**)&pz2,  g_z2);
    cudaGetSymbolAddress((void**)&pxz,  g_xz);
    cudaGetSymbolAddress((void**)&pt1,  g_t1);
    cudaGetSymbolAddress((void**)&pt2,  g_t2b);
    cudaGetSymbolAddress((void**)&ppart,g_part);
    cudaGetSymbolAddress((void**)&pa3v, g_a3v);
    cudaGetSymbolAddress((void**)&pW,   g_W);
    cudaGetSymbolAddress((void**)&pscal,g_scal);

    cudaFuncSetAttribute(attn1_kernel, cudaFuncAttributeMaxDynamicSharedMemorySize, 110592);

    // side stream + fork/join events (resource init once; identical GPU work per call)
    static cudaStream_t s2 = 0;
    static cudaEvent_t evF = 0, evJ = 0;
    if (!s2) {
        cudaStreamCreateWithFlags(&s2, cudaStreamNonBlocking);
        cudaEventCreateWithFlags(&evF, cudaEventDisableTiming);
        cudaEventCreateWithFlags(&evJ, cudaEventDisableTiming);
    }
    cudaStream_t s0 = 0;

    // h[1:] = relu(x @ fc_w + fc_b); h[0] = cls
    GEMM128(false,true,true,false,false,false, dim3(4,128,1), s0,
            x, fc_w, fc_b, ph+DIMF, F0,F0,F0,F0, NX,512,1024, 1024,512,512, 0,0,0);
    copy_cls_kernel<<<2,256,0,s0>>>(cls, ph);

    for (int l=0;l<2;l++) {
        const float *nw=Lp[l][0], *nb=Lp[l][1], *qw=Lp[l][2],
                    *ow=Lp[l][3], *ob=Lp[l][4], *rk=Lp[l][5];

        // LN stats + fused-LN qkv GEMM (q pre-scaled by 1/8)
        ln_stats_kernel<<<N_TOK,256,0,s0>>>(ph, pmu, prstd);
        GEMM128(false,false,false,false,true,true, dim3(12,128,1), s0,
                ph, qw, F0, pqkv, nw,nb,pmu,prstd, N_TOK,QKV3,512, 512,QKV3,QKV3, 0,0,0);
        landmark_kernel<<<2048,64,0,s0>>>(pqkv, pql, pkl);
        attn2_kernel<<<2048,256,0,s0>>>(pql, pkl, pa2);

        // ---- fork: pinv chain on s2, attn3 chain on s0 ----
        cudaEventRecord(evF, s0);
        cudaStreamWaitEvent(s2, evF, 0);

        // pinv chain (s2)
        zero_scal_kernel<<<1,32,0,s2>>>(pscal);
        pinv_max_kernel<<<4096,256,0,s2>>>(pa2, pscal);
        zinit_kernel<<<2048,256,0,s2>>>(pa2, pscal, pz);
        float* zc = pz; float* zo = pz2;
        for (int it=0; it<6; it++) {
            GEMM(false,false,false,false,false,true,false,false, dim3(4,4,8), s2,
                 pa2, zc, F0, pxz, F0,F0,F0,F0, 256,256,256, 256,256,256, 65536,65536,65536, 1, 1.f,0.f,1.f);
            GEMM(false,false,false,false,false,true,false,false, dim3(4,4,8), s2,
                 pxz, pxz, F0, pt1, F0,F0,F0,F0, 256,256,256, 256,256,256, 65536,65536,65536, 1, 1.f,7.f,-1.f);
            GEMM(false,false,false,false,false,true,false,false, dim3(4,4,8), s2,
                 pxz, pt1, F0, pt2, F0,F0,F0,F0, 256,256,256, 256,256,256, 65536,65536,65536, 1, 1.f,15.f,-1.f);
            GEMM(false,false,false,false,false,true,false,false, dim3(4,4,8), s2,
                 zc, pt2, F0, zo, F0,F0,F0,F0, 256,256,256, 256,256,256, 65536,65536,65536, 1, 0.25f,13.f,-1.f);
            float* tmp=zc; zc=zo; zo=tmp;
        }

        // attn3 chain (s0): 2 heads per batch; softmax fused into a3v A-load
        for (int h0=0; h0<NH; h0+=2) {
            GEMM128(true,false,false,false,false,false, dim3(128,2,2), s0,
                    pql + h0*ML*DH, pqkv+512+h0*64, F0, ps3, F0,F0,F0,F0,
                    256,N_TOK,64, 64,QKV3,N_TOK, ML*DH,64,(long)ML*N_TOK);
            softmax_stats_kernel<<<2*ML,256,0,s0>>>(ps3, N_TOK, psm, psrv);
            GEMM(false,false,false,false,false,false,false,true, dim3(1,4,2*32), s0,
                 ps3, pqkv+1024+h0*64, F0, ppart, F0,F0,psm,psrv,
                 256,64,N_TOK, N_TOK,QKV3,64, (long)ML*N_TOK,64,ML*DH, 32, 1.f,0.f,1.f);
            reduce_part_kernel<<<(2*ML*DH+255)/256,256,0,s0>>>(ppart, pa3v + h0*ML*DH, 32, ML*DH, 2);
        }

        // ---- join ----
        cudaEventRecord(evJ, s2);
        cudaStreamWaitEvent(s0, evJ, 0);

        // W = pinv @ a3v  (batched over heads, split-K 4)
        GEMM(false,false,false,false,false,false,false,false, dim3(1,4,8*4), s0,
             zc, pa3v, F0, ppart, F0,F0,F0,F0,
             256,64,256, 256,64,64, 65536,ML*DH,ML*DH, 4, 1.f,0.f,1.f);
        reduce_part_kernel<<<(NH*ML*DH+255)/256,256,0,s0>>>(ppart, pW, 4, ML*DH, NH);

        // fused: q-slot of qkv <- softmax(q @ k_l^T) @ W
        attn1_kernel<<<dim3(512,NH),256,110592,s0>>>(pqkv, pkl, pW);
        // + depthwise residual conv of v
        conv_kernel<<<(N_TOK*DIMF)/256,256,0,s0>>>(pqkv, rk);
        // h += attn_out @ out_w + out_b
        GEMM128(false,true,false,true,false,false, dim3(4,128,1), s0,
                pqkv, ow, ob, ph, F0,F0,F0,F0, N_TOK,512,512, 1536,512,512, 0,0,0);
    }

    final_kernel<<<1,512,0,s0>>>(ph, norm_w, norm_b, clf_w, clf_b, out);
}

// round 17
// speedup vs baseline: 3.0000x; 1.1999x over previous
#include <cuda_runtime.h>
#include <math.h>

// ---------------- problem constants ----------------
#define N_TOK 16384
#define NX    16383
#define DIMF  512
#define NH    8
#define DH    64
#define ML    256      // landmarks
#define QKV3  1536

typedef unsigned long long ull;

// packed f32x2 helpers
__device__ __forceinline__ ull ffma2(ull a, ull b, ull c){
    ull d; asm("fma.rn.f32x2 %0,%1,%2,%3;" : "=l"(d) : "l"(a), "l"(b), "l"(c)); return d;
}
__device__ __forceinline__ ull pack2(float x, float y){
    ull d; asm("mov.b64 %0,{%1,%2};" : "=l"(d) : "f"(x), "f"(y)); return d;
}
__device__ __forceinline__ float2 unpack2(ull v){
    float2 r; asm("mov.b64 {%0,%1},%2;" : "=f"(r.x), "=f"(r.y) : "l"(v)); return r;
}
// tf32 helpers
__device__ __forceinline__ unsigned f2tf(float x){
    unsigned r; asm("cvt.rna.tf32.f32 %0, %1;" : "=r"(r) : "f"(x)); return r;
}
__device__ __forceinline__ void mma_tf32(float* c, const unsigned* a, const unsigned* b){
    asm volatile("mma.sync.aligned.m16n8k8.row.col.f32.tf32.tf32.f32 "
        "{%0,%1,%2,%3}, {%4,%5,%6,%7}, {%8,%9}, {%0,%1,%2,%3};"
        : "+f"(c[0]), "+f"(c[1]), "+f"(c[2]), "+f"(c[3])
        : "r"(a[0]), "r"(a[1]), "r"(a[2]), "r"(a[3]), "r"(b[0]), "r"(b[1]));
}

// ---------------- scratch (device globals; ~185 MB total) ----------------
__device__ float g_h   [N_TOK*DIMF];
__device__ float g_qkv [N_TOK*QKV3];        // q|k|v (q slot reused for attn out)
__device__ float g_s3h [2*ML*N_TOK];        // 2-head batched attn3 raw scores
__device__ float g_mu  [N_TOK];
__device__ float g_rstd[N_TOK];
__device__ float g_sm  [2*ML];              // softmax row max
__device__ float g_srv [2*ML];              // softmax row 1/sum
__device__ float g_ql  [NH*ML*DH];
__device__ float g_kl  [NH*ML*DH];
__device__ float g_a2  [NH*ML*ML];
__device__ float g_z   [NH*ML*ML];
__device__ float g_z2  [NH*ML*ML];
__device__ float g_xz  [NH*ML*ML];
__device__ float g_t1  [NH*ML*ML];
__device__ float g_t2b [NH*ML*ML];
__device__ float g_part[64*ML*DH];
__device__ float g_a3v [NH*ML*DH];
__device__ float g_W   [NH*ML*DH];
__device__ float g_scal[2];

// ====== 128x128x16 GEMM via tf32 mma.sync; operands stored in smem as tf32 bits ======
#define TM 128
#define TN 128
#define TK 16
#define SMS 136   // smem row stride

template<bool TRANSB, bool BIAS, bool RELU, bool ACCUM, bool QSCALE, bool LNA>
__global__ __launch_bounds__(256)
void gemm128_kernel(const float* __restrict__ A, const float* __restrict__ B,
                    const float* __restrict__ bias, float* __restrict__ C,
                    const float* __restrict__ lnw, const float* __restrict__ lnb,
                    const float* __restrict__ mu,  const float* __restrict__ rstd,
                    int Mm, int Nn, int Kk, int lda, int ldb, int ldc,
                    long sA, long sB, long sC)
{
    __shared__ unsigned As[TK][SMS];
    __shared__ unsigned Bs[TK][SMS];
    int z = blockIdx.z;
    const float* Ab = A + (long)z * sA;
    const float* Bb = B + (long)z * sB;
    float* Cb = C + (long)z * sC;
    int m0 = blockIdx.y * TM;
    int n0 = blockIdx.x * TN;
    int tid = threadIdx.x;
    int lane = tid & 31, warp = tid >> 5;
    int wm = warp & 1, wn = warp >> 1;       // warp tile: 64m x 32n
    int row = lane >> 2, tg = lane & 3;

    float acc[4][4][4];
#pragma unroll
    for (int mt=0;mt<4;mt++)
#pragma unroll
        for (int nt=0;nt<4;nt++)
#pragma unroll
            for (int f=0;f<4;f++) acc[mt][nt][f]=0.f;

    for (int kt = 0; kt < Kk; kt += TK) {
        // ---- A tile: 128 rows x 16 k (tf32 at store) ----
#pragma unroll
        for (int l = 0; l < 2; l++) {
            int i = tid + l*256;
            int m = i >> 2, kq = i & 3;
            int gm = m0 + m, gk = kt + kq*4;
            float4 v = make_float4(0.f,0.f,0.f,0.f);
            if (gm < Mm) {
                v = *reinterpret_cast<const float4*>(&Ab[(long)gm*lda + gk]);
                if (LNA) {
                    float mm = mu[gm], rr = rstd[gm];
                    v.x = (v.x-mm)*rr*lnw[gk+0] + lnb[gk+0];
                    v.y = (v.y-mm)*rr*lnw[gk+1] + lnb[gk+1];
                    v.z = (v.z-mm)*rr*lnw[gk+2] + lnb[gk+2];
                    v.w = (v.w-mm)*rr*lnw[gk+3] + lnb[gk+3];
                }
            }
            As[kq*4+0][m] = f2tf(v.x);
            As[kq*4+1][m] = f2tf(v.y);
            As[kq*4+2][m] = f2tf(v.z);
            As[kq*4+3][m] = f2tf(v.w);
        }
        // ---- B tile ----
        if (TRANSB) {
#pragma unroll
            for (int l = 0; l < 2; l++) {
                int i = tid + l*256;
                int n = i >> 2, kq = i & 3;
                int gn = n0 + n, gk = kt + kq*4;
                float4 v = *reinterpret_cast<const float4*>(&Bb[(long)gn*ldb + gk]);
                Bs[kq*4+0][n] = f2tf(v.x);
                Bs[kq*4+1][n] = f2tf(v.y);
                Bs[kq*4+2][n] = f2tf(v.z);
                Bs[kq*4+3][n] = f2tf(v.w);
            }
        } else {
#pragma unroll
            for (int l = 0; l < 2; l++) {
                int i = tid + l*256;
                int kk = i >> 5, nq = i & 31;
                int gn = n0 + nq*4, gk = kt + kk;
                float4 v = *reinterpret_cast<const float4*>(&Bb[(long)gk*ldb + gn]);
                uint4 u = make_uint4(f2tf(v.x), f2tf(v.y), f2tf(v.z), f2tf(v.w));
                *reinterpret_cast<uint4*>(&Bs[kk][nq*4]) = u;
            }
        }
        __syncthreads();
        // ---- two k8 MMA steps (pure LDS + MMA) ----
#pragma unroll
        for (int ks = 0; ks < 2; ks++) {
            int k0 = ks*8;
            unsigned afr[4][4], bfr[4][2];
#pragma unroll
            for (int mt=0;mt<4;mt++){
                int mb = wm*64 + mt*16;
                afr[mt][0] = As[k0+tg  ][mb+row];
                afr[mt][1] = As[k0+tg  ][mb+row+8];
                afr[mt][2] = As[k0+tg+4][mb+row];
                afr[mt][3] = As[k0+tg+4][mb+row+8];
            }
#pragma unroll
            for (int nt=0;nt<4;nt++){
                int nb = wn*32 + nt*8;
                bfr[nt][0] = Bs[k0+tg  ][nb+row];
                bfr[nt][1] = Bs[k0+tg+4][nb+row];
            }
#pragma unroll
            for (int mt=0;mt<4;mt++)
#pragma unroll
                for (int nt=0;nt<4;nt++)
                    mma_tf32(acc[mt][nt], afr[mt], bfr[nt]);
        }
        __syncthreads();
    }
    // ---- epilogue ----
#pragma unroll
    for (int mt=0;mt<4;mt++){
#pragma unroll
        for (int half=0; half<2; half++){
            int gm = m0 + wm*64 + mt*16 + row + half*8;
            if (gm >= Mm) continue;
            long rowoff = (long)gm*ldc;
#pragma unroll
            for (int nt=0;nt<4;nt++){
                int gn = n0 + wn*32 + nt*8 + 2*tg;
                float v0 = acc[mt][nt][half*2+0];
                float v1 = acc[mt][nt][half*2+1];
                if (QSCALE) { if (gn < 512) v0 *= 0.125f; if (gn+1 < 512) v1 *= 0.125f; }
                if (BIAS)   { v0 += bias[gn]; v1 += bias[gn+1]; }
                if (RELU)   { v0 = fmaxf(v0,0.f); v1 = fmaxf(v1,0.f); }
                if (ACCUM)  { Cb[rowoff+gn] += v0; Cb[rowoff+gn+1] += v1; }
                else        { Cb[rowoff+gn]  = v0; Cb[rowoff+gn+1]  = v1; }
            }
        }
    }
}

// ================= 64x64x16 GEMM (pinv / a3v / W paths) =================
#define BM 64
#define BN 64
#define BK 16

template<bool TRANSB, bool BIAS, bool RELU, bool ACCUM, bool QSCALE, bool DIAGB, bool LNA, bool EXPA>
__global__ __launch_bounds__(256)
void gemm_kernel(const float* __restrict__ A, const float* __restrict__ B,
                 const float* __restrict__ bias, float* __restrict__ C,
                 const float* __restrict__ lnw, const float* __restrict__ lnb,
                 const float* __restrict__ mu,  const float* __restrict__ rstd,
                 int Mm, int Nn, int Kk, int lda, int ldb, int ldc,
                 long sA, long sB, long sC, int kchunks,
                 float alpha, float dbeta, float bsign)
{
    __shared__ float As[BK][BM+1];
    __shared__ float Bs[BK][BN+1];
    int z = blockIdx.z;
    int batch = z / kchunks;
    int chunk = z - batch*kchunks;
    const float* Ab = A + (long)batch * sA;
    const float* Bb = B + (long)batch * sB;
    float* Cb = C + (long)z * sC;
    int kPer   = Kk / kchunks;
    int kstart = chunk * kPer;
    int m0 = blockIdx.y * BM;
    int n0 = blockIdx.x * BN;
    int tid = threadIdx.x;
    int tx = tid & 15, ty = tid >> 4;
    float acc[4][4];
#pragma unroll
    for (int i=0;i<4;i++)
#pragma unroll
        for (int j=0;j<4;j++) acc[i][j]=0.f;

    for (int kt = kstart; kt < kstart + kPer; kt += BK) {
#pragma unroll
        for (int l = 0; l < 4; l++) {
            int i  = tid + l*256;
            int m  = i >> 4, kk = i & 15;
            int gm = m0 + m, gk = kt + kk;
            float v = 0.f;
            if (gm < Mm && gk < Kk) {
                v = Ab[(long)gm*lda + gk];
                if (LNA)  v = (v - mu[gm]) * rstd[gm] * lnw[gk] + lnb[gk];
                if (EXPA) v = __expf(v - mu[(long)batch*Mm + gm]) * rstd[(long)batch*Mm + gm];
            }
            As[kk][m] = v;
        }
#pragma unroll
        for (int l = 0; l < 4; l++) {
            int i = tid + l*256;
            float v; int kk, n;
            if (TRANSB) {
                n = i >> 4; kk = i & 15;
                int gn = n0 + n, gk = kt + kk;
                v = (gn < Nn && gk < Kk) ? Bb[(long)gn*ldb + gk] : 0.f;
            } else {
                kk = i >> 6; n = i & 63;
                int gn = n0 + n, gk = kt + kk;
                v = (gn < Nn && gk < Kk) ? Bb[(long)gk*ldb + gn] : 0.f;
                if (DIAGB) v = dbeta*((gk==gn)?1.f:0.f) + bsign*v;
            }
            Bs[kk][n] = v;
        }
        __syncthreads();
#pragma unroll
        for (int kk = 0; kk < BK; kk++) {
            float a[4], b[4];
#pragma unroll
            for (int i=0;i<4;i++) a[i] = As[kk][ty*4+i];
#pragma unroll
            for (int j=0;j<4;j++) b[j] = Bs[kk][tx*4+j];
#pragma unroll
            for (int i=0;i<4;i++)
#pragma unroll
                for (int j=0;j<4;j++) acc[i][j] += a[i]*b[j];
        }
        __syncthreads();
    }
#pragma unroll
    for (int i=0;i<4;i++) {
        int gm = m0 + ty*4 + i;
        if (gm >= Mm) continue;
#pragma unroll
        for (int j=0;j<4;j++) {
            int gn = n0 + tx*4 + j;
            if (gn >= Nn) continue;
            float v = alpha * acc[i][j];
            if (QSCALE && gn < 512) v *= 0.125f;
            if (BIAS) v += bias[gn];
            if (RELU) v = fmaxf(v, 0.f);
            long idx = (long)gm*ldc + gn;
            if (ACCUM) Cb[idx] += v; else Cb[idx] = v;
        }
    }
}

// ---------------- small kernels ----------------
__global__ void copy_cls_kernel(const float* __restrict__ c, float* __restrict__ h){
    int i = blockIdx.x*256 + threadIdx.x;
    if (i < DIMF) h[i] = c[i];
}

__global__ void ln_stats_kernel(const float* __restrict__ x, float* __restrict__ mu,
                                float* __restrict__ rstd)
{
    __shared__ float red[256];
    int row = blockIdx.x, tid = threadIdx.x;
    const float* xr = x + (long)row*DIMF;
    float v0 = xr[tid], v1 = xr[tid+256];
    red[tid] = v0+v1; __syncthreads();
    for (int s=128;s;s>>=1){ if(tid<s) red[tid]+=red[tid+s]; __syncthreads(); }
    float m = red[0]*(1.f/512.f); __syncthreads();
    float d0 = v0-m, d1 = v1-m;
    red[tid] = d0*d0+d1*d1; __syncthreads();
    for (int s=128;s;s>>=1){ if(tid<s) red[tid]+=red[tid+s]; __syncthreads(); }
    if (tid==0){ mu[row]=m; rstd[row]=rsqrtf(red[0]*(1.f/512.f)+1e-5f); }
}

__global__ void landmark_kernel(const float* __restrict__ qkv,
                                float* __restrict__ ql, float* __restrict__ kl)
{
    int b = blockIdx.x; int hd = b >> 8; int j = b & 255;
    int d = threadIdx.x;
    float sq = 0.f, sk = 0.f;
    long base = (long)(j*64)*QKV3 + hd*64 + d;
#pragma unroll 4
    for (int i=0;i<64;i++){ sq += qkv[base + (long)i*QKV3]; sk += qkv[base + (long)i*QKV3 + 512]; }
    ql[((hd<<8)+j)*64 + d] = sq*(1.f/64.f);
    kl[((hd<<8)+j)*64 + d] = sk*(1.f/64.f);
}

__global__ void attn2_kernel(const float* __restrict__ ql, const float* __restrict__ kl,
                             float* __restrict__ out)
{
    __shared__ float qrow[64];
    __shared__ float red[256];
    int b = blockIdx.x; int hd = b >> 8; int j = b & 255;
    int tid = threadIdx.x;
    if (tid < 64) qrow[tid] = ql[((hd<<8)+j)*64 + tid];
    __syncthreads();
    const float* krow = kl + ((long)((hd<<8)+tid))*64;
    float acc = 0.f;
#pragma unroll 8
    for (int d=0; d<64; d++) acc += qrow[d]*krow[d];
    red[tid]=acc; __syncthreads();
    for (int s=128;s;s>>=1){ if(tid<s) red[tid]=fmaxf(red[tid],red[tid+s]); __syncthreads(); }
    float mx = red[0]; __syncthreads();
    float e = expf(acc - mx);
    red[tid]=e; __syncthreads();
    for (int s=128;s;s>>=1){ if(tid<s) red[tid]+=red[tid+s]; __syncthreads(); }
    out[((long)((hd<<8)+j))*256 + tid] = e * (1.f/red[0]);
}

__global__ void zero_scal_kernel(float* s){ if (threadIdx.x < 2) s[threadIdx.x] = 0.f; }

__global__ void pinv_max_kernel(const float* __restrict__ x, float* __restrict__ scal)
{
    __shared__ float red[256];
    int b = blockIdx.x, tid = threadIdx.x;
    float s;
    if (b < 2048) { int hd=b>>8, i=b&255; s = x[(((long)(hd<<8)+i)<<8) + tid]; }
    else { int bb=b-2048; int hd=bb>>8, j=bb&255; s = x[(((long)(hd<<8)+tid)<<8) + j]; }
    red[tid]=s; __syncthreads();
    for (int st=128;st;st>>=1){ if(tid<st) red[tid]+=red[tid+st]; __syncthreads(); }
    if (tid==0) atomicMax((int*)&scal[b<2048?0:1], __float_as_int(red[0]));
}

__global__ void zinit_kernel(const float* __restrict__ x, const float* __restrict__ scal,
                             float* __restrict__ z)
{
    int b = blockIdx.x; int hd=b>>8, i=b&255; int j=threadIdx.x;
    float inv = 1.f/(scal[0]*scal[1]);
    z[(((long)(hd<<8)+i)<<8)+j] = x[(((long)(hd<<8)+j)<<8)+i] * inv;
}

// softmax row stats only: max + 1/sum(exp(x-max))
__global__ void softmax_stats_kernel(const float* __restrict__ s, int n,
                                     float* __restrict__ m_out, float* __restrict__ rv_out)
{
    __shared__ float red[256];
    long base = (long)blockIdx.x * n;
    int tid = threadIdx.x;
    float mx = -1e30f;
    for (int i=tid;i<n;i+=256) mx = fmaxf(mx, s[base+i]);
    red[tid]=mx; __syncthreads();
    for (int st=128;st;st>>=1){ if(tid<st) red[tid]=fmaxf(red[tid],red[tid+st]); __syncthreads(); }
    mx = red[0]; __syncthreads();
    float sum=0.f;
    for (int i=tid;i<n;i+=256) sum += __expf(s[base+i]-mx);
    red[tid]=sum; __syncthreads();
    for (int st=128;st;st>>=1){ if(tid<st) red[tid]+=red[tid+st]; __syncthreads(); }
    if (tid==0){ m_out[blockIdx.x]=mx; rv_out[blockIdx.x]=1.f/red[0]; }
}

__global__ void reduce_part_kernel(const float* __restrict__ part, float* __restrict__ out,
                                   int chunks, int sz, int nb)
{
    long idx = (long)blockIdx.x*256 + threadIdx.x;
    if (idx >= (long)nb*sz) return;
    int b = (int)(idx / sz); int r = (int)(idx - (long)b*sz);
    float s = 0.f;
    for (int c=0;c<chunks;c++) s += part[((long)(b*chunks+c))*sz + r];
    out[idx] = s;
}

// fused attn1 @ W : 32 tokens x 1 head per block; tf32 MMA phases 1 & 3.
#define KLS_STRIDE 68
#define QS_STRIDE  68
#define SS_STRIDE  260
// smem floats: 256*68 + 32*68 + 32*260 = 27904 floats = 111616 bytes
#define ATTN1_SMEM 111616

__global__ void attn1_kernel(float* __restrict__ qkv, const float* __restrict__ kl,
                             const float* __restrict__ W)
{
    extern __shared__ float sm[];
    unsigned* kls = reinterpret_cast<unsigned*>(sm);            // 256 x 68 (tf32 bits)
    unsigned* qs  = reinterpret_cast<unsigned*>(sm) + 256*KLS_STRIDE; // 32 x 68
    float* ss  = sm + 256*KLS_STRIDE + 32*QS_STRIDE;            // 32 x 260
    int hd = blockIdx.y;
    int i0 = blockIdx.x * 32;
    int tid = threadIdx.x;
    int lane = tid & 31, warp = tid >> 5;
    int row = lane >> 2, tg = lane & 3;

    for (int idx = tid; idx < 256*64; idx += 256) {
        int c = idx >> 6, d = idx & 63;
        kls[c*KLS_STRIDE+d] = f2tf(kl[((long)((hd<<8)+c))*64 + d]);
    }
    for (int idx = tid; idx < 32*64; idx += 256) {
        int r = idx >> 6, d = idx & 63;
        qs[r*QS_STRIDE+d] = f2tf(qkv[(long)(i0+r)*QKV3 + hd*64 + d]);
    }
    __syncthreads();
    // phase 1: ss(32x256) = q @ kl^T via MMA; warp covers n-slice of 32
    {
        int nb0 = warp*32;
        float acc[2][4][4];
#pragma unroll
        for (int mt=0;mt<2;mt++)
#pragma unroll
            for (int nt=0;nt<4;nt++)
#pragma unroll
                for (int f=0;f<4;f++) acc[mt][nt][f]=0.f;
#pragma unroll
        for (int k0 = 0; k0 < 64; k0 += 8) {
            unsigned afr[2][4], bfr[4][2];
#pragma unroll
            for (int mt=0;mt<2;mt++){
                int mb = mt*16;
                afr[mt][0] = qs[(mb+row  )*QS_STRIDE + k0+tg];
                afr[mt][1] = qs[(mb+row+8)*QS_STRIDE + k0+tg];
                afr[mt][2] = qs[(mb+row  )*QS_STRIDE + k0+tg+4];
                afr[mt][3] = qs[(mb+row+8)*QS_STRIDE + k0+tg+4];
            }
#pragma unroll
            for (int nt=0;nt<4;nt++){
                int nn = nb0 + nt*8 + row;
                bfr[nt][0] = kls[nn*KLS_STRIDE + k0+tg];
                bfr[nt][1] = kls[nn*KLS_STRIDE + k0+tg+4];
            }
#pragma unroll
            for (int mt=0;mt<2;mt++)
#pragma unroll
                for (int nt=0;nt<4;nt++)
                    mma_tf32(acc[mt][nt], afr[mt], bfr[nt]);
        }
#pragma unroll
        for (int mt=0;mt<2;mt++)
#pragma unroll
            for (int nt=0;nt<4;nt++){
                int cc = nb0 + nt*8 + 2*tg;
                ss[(mt*16+row  )*SS_STRIDE + cc  ] = acc[mt][nt][0];
                ss[(mt*16+row  )*SS_STRIDE + cc+1] = acc[mt][nt][1];
                ss[(mt*16+row+8)*SS_STRIDE + cc  ] = acc[mt][nt][2];
                ss[(mt*16+row+8)*SS_STRIDE + cc+1] = acc[mt][nt][3];
            }
    }
    __syncthreads();
    // phase 2: softmax per row (warp handles 4 rows)
    {
        for (int r = warp*4; r < warp*4+4; r++) {
            float mx = -1e30f;
#pragma unroll
            for (int k=0;k<8;k++) mx = fmaxf(mx, ss[r*SS_STRIDE + lane + 32*k]);
            for (int o=16;o;o>>=1) mx = fmaxf(mx, __shfl_xor_sync(0xffffffffu, mx, o));
            float sum = 0.f;
#pragma unroll
            for (int k=0;k<8;k++){ float e = __expf(ss[r*SS_STRIDE+lane+32*k]-mx); ss[r*SS_STRIDE+lane+32*k]=e; sum+=e; }
            for (int o=16;o;o>>=1) sum += __shfl_xor_sync(0xffffffffu, sum, o);
            float inv = 1.f/sum;
#pragma unroll
            for (int k=0;k<8;k++) ss[r*SS_STRIDE+lane+32*k] *= inv;
        }
    }
    __syncthreads();
    // phase 3: out(32x64) = P @ W via MMA; warp covers n-slice of 8
    {
        int nb = warp*8;
        const float* Wh = W + (long)hd*ML*DH;
        float acc[2][4];
#pragma unroll
        for (int mt=0;mt<2;mt++)
#pragma unroll
            for (int f=0;f<4;f++) acc[mt][f]=0.f;
        for (int k0 = 0; k0 < 256; k0 += 8) {
            unsigned afr[2][4], bfr[2];
#pragma unroll
            for (int mt=0;mt<2;mt++){
                int mb = mt*16;
                afr[mt][0] = f2tf(ss[(mb+row  )*SS_STRIDE + k0+tg]);
                afr[mt][1] = f2tf(ss[(mb+row+8)*SS_STRIDE + k0+tg]);
                afr[mt][2] = f2tf(ss[(mb+row  )*SS_STRIDE + k0+tg+4]);
                afr[mt][3] = f2tf(ss[(mb+row+8)*SS_STRIDE + k0+tg+4]);
            }
            bfr[0] = f2tf(Wh[(k0+tg  )*64 + nb+row]);
            bfr[1] = f2tf(Wh[(k0+tg+4)*64 + nb+row]);
#pragma unroll
            for (int mt=0;mt<2;mt++)
                mma_tf32(acc[mt], afr[mt], bfr);
        }
#pragma unroll
        for (int mt=0;mt<2;mt++){
            int d0 = nb + 2*tg;
            long a0 = (long)(i0 + mt*16 + row)*QKV3 + hd*64;
            long a1 = (long)(i0 + mt*16 + row + 8)*QKV3 + hd*64;
            qkv[a0 + d0    ] = acc[mt][0];
            qkv[a0 + d0 + 1] = acc[mt][1];
            qkv[a1 + d0    ] = acc[mt][2];
            qkv[a1 + d0 + 1] = acc[mt][3];
        }
    }
}

// depthwise residual conv over sequence: qkv q-slot += conv(v, res_k)
__global__ void conv_kernel(float* __restrict__ qkv, const float* __restrict__ rk)
{
    __shared__ float rks[NH*33];
    int tid = threadIdx.x;
    for (int i = tid; i < NH*33; i += 256) rks[i] = rk[i];
    __syncthreads();
    long idx = (long)blockIdx.x*256 + tid;
    int i = (int)(idx >> 9); int col = (int)(idx & 511); int hd = col >> 6;
    long addr = (long)i*QKV3 + col;
    float acc = qkv[addr];
#pragma unroll
    for (int t=0;t<33;t++){
        int ii = i + t - 16;
        if (ii >= 0 && ii < N_TOK)
            acc += rks[hd*33+t] * qkv[(long)ii*QKV3 + 1024 + col];
    }
    qkv[addr] = acc;
}

// final: LN on row 0 -> clf -> sigmoid -> cumprod survival
__global__ void final_kernel(const float* __restrict__ h, const float* __restrict__ nw,
                             const float* __restrict__ nb, const float* __restrict__ cw,
                             const float* __restrict__ cb, float* __restrict__ out)
{
    __shared__ float red[512];
    __shared__ float xn[512];
    __shared__ float lg[4];
    int tid = threadIdx.x;
    float v = h[tid];
    red[tid]=v; __syncthreads();
    for (int s=256;s;s>>=1){ if(tid<s) red[tid]+=red[tid+s]; __syncthreads(); }
    float mu = red[0]*(1.f/512.f); __syncthreads();
    float d = v-mu;
    red[tid]=d*d; __syncthreads();
    for (int s=256;s;s>>=1){ if(tid<s) red[tid]+=red[tid+s]; __syncthreads(); }
    float rstd = rsqrtf(red[0]*(1.f/512.f) + 1e-5f);
    xn[tid] = d*rstd*nw[tid] + nb[tid];
    __syncthreads();
    if (tid < 128) {
        int c = tid >> 5, lane = tid & 31;
        float s = 0.f;
        for (int k=lane;k<512;k+=32) s += xn[k]*cw[k*4+c];
        for (int o=16;o;o>>=1) s += __shfl_xor_sync(0xffffffffu, s, o);
        if (lane==0) lg[c] = s + cb[c];
    }
    __syncthreads();
    if (tid==0) {
        float S = 1.f;
        for (int c=0;c<4;c++){
            float hz = 1.f/(1.f+expf(-lg[c]));
            out[c] = hz;
            S *= (1.f - hz);
            out[4+c] = S;
        }
    }
}

// ---------------- host launch ----------------
#define GEMM(TB,BI,RE,AC,QS,DG,LN,EX, grid, st, A,B,bias,C, lnw,lnb,mu,rstd, M,N,K, lda,ldb,ldc, sA,sB,sC, kch, al,db,bs) \
    gemm_kernel<TB,BI,RE,AC,QS,DG,LN,EX><<<grid, 256, 0, st>>>(A,B,bias,C,lnw,lnb,mu,rstd,M,N,K,lda,ldb,ldc,(long)(sA),(long)(sB),(long)(sC),kch,al,db,bs)

#define GEMM128(TB,BI,RE,AC,QS,LN, grid, st, A,B,bias,C, lnw,lnb,mu,rstd, M,N,K, lda,ldb,ldc, sA,sB,sC) \
    gemm128_kernel<TB,BI,RE,AC,QS,LN><<<grid, 256, 0, st>>>(A,B,bias,C,lnw,lnb,mu,rstd,M,N,K,lda,ldb,ldc,(long)(sA),(long)(sB),(long)(sC))

extern "C" void kernel_launch(void* const* d_in, const int* in_sizes, int n_in,
                              void* d_out, int out_size)
{
    const float* x     = (const float*)d_in[0];
    const float* fc_w  = (const float*)d_in[1];
    const float* fc_b  = (const float*)d_in[2];
    const float* cls   = (const float*)d_in[3];
    const float* Lp[2][6];
    for (int l=0;l<2;l++) for (int k=0;k<6;k++) Lp[l][k] = (const float*)d_in[4 + l*6 + k];
    const float* norm_w = (const float*)d_in[16];
    const float* norm_b = (const float*)d_in[17];
    const float* clf_w  = (const float*)d_in[18];
    const float* clf_b  = (const float*)d_in[19];
    float* out = (float*)d_out;
    const float* F0 = 0;

    float *ph,*pqkv,*ps3,*pmu,*prstd,*psm,*psrv,*pql,*pkl,*pa2,*pz,*pz2,*pxz,*pt1,*pt2,*ppart,*pa3v,*pW,*pscal;
    cudaGetSymbolAddress((void**)&ph,   g_h);
    cudaGetSymbolAddress((void**)&pqkv, g_qkv);
    cudaGetSymbolAddress((void**)&ps3,  g_s3h);
    cudaGetSymbolAddress((void**)&pmu,  g_mu);
    cudaGetSymbolAddress((void**)&prstd,g_rstd);
    cudaGetSymbolAddress((void**)&psm,  g_sm);
    cudaGetSymbolAddress((void**)&psrv, g_srv);
    cudaGetSymbolAddress((void**)&pql,  g_ql);
    cudaGetSymbolAddress((void**)&pkl,  g_kl);
    cudaGetSymbolAddress((void**)&pa2,  g_a2);
    cudaGetSymbolAddress((void**)&pz,   g_z);
    cudaGetSymbolAddress((void**)&pz2,  g_z2);
    cudaGetSymbolAddress((void**)&pxz,  g_xz);
    cudaGetSymbolAddress((void**)&pt1,  g_t1);
    cudaGetSymbolAddress((void**)&pt2,  g_t2b);
    cudaGetSymbolAddress((void**)&ppart,g_part);
    cudaGetSymbolAddress((void**)&pa3v, g_a3v);
    cudaGetSymbolAddress((void**)&pW,   g_W);
    cudaGetSymbolAddress((void**)&pscal,g_scal);

    cudaFuncSetAttribute(attn1_kernel, cudaFuncAttributeMaxDynamicSharedMemorySize, ATTN1_SMEM);

    // side stream + fork/join events (resource init once; identical GPU work per call)
    static cudaStream_t s2 = 0;
    static cudaEvent_t evF = 0, evJ = 0;
    if (!s2) {
        cudaStreamCreateWithFlags(&s2, cudaStreamNonBlocking);
        cudaEventCreateWithFlags(&evF, cudaEventDisableTiming);
        cudaEventCreateWithFlags(&evJ, cudaEventDisableTiming);
    }
    cudaStream_t s0 = 0;

    // h[1:] = relu(x @ fc_w + fc_b); h[0] = cls
    GEMM128(false,true,true,false,false,false, dim3(4,128,1), s0,
            x, fc_w, fc_b, ph+DIMF, F0,F0,F0,F0, NX,512,1024, 1024,512,512, 0,0,0);
    copy_cls_kernel<<<2,256,0,s0>>>(cls, ph);

    for (int l=0;l<2;l++) {
        const float *nw=Lp[l][0], *nb=Lp[l][1], *qw=Lp[l][2],
                    *ow=Lp[l][3], *ob=Lp[l][4], *rk=Lp[l][5];

        // LN stats + fused-LN qkv GEMM (q pre-scaled by 1/8)
        ln_stats_kernel<<<N_TOK,256,0,s0>>>(ph, pmu, prstd);
        GEMM128(false,false,false,false,true,true, dim3(12,128,1), s0,
                ph, qw, F0, pqkv, nw,nb,pmu,prstd, N_TOK,QKV3,512, 512,QKV3,QKV3, 0,0,0);
        landmark_kernel<<<2048,64,0,s0>>>(pqkv, pql, pkl);
        attn2_kernel<<<2048,256,0,s0>>>(pql, pkl, pa2);

        // ---- fork: pinv chain on s2, attn3 chain on s0 ----
        cudaEventRecord(evF, s0);
        cudaStreamWaitEvent(s2, evF, 0);

        // pinv chain (s2)
        zero_scal_kernel<<<1,32,0,s2>>>(pscal);
        pinv_max_kernel<<<4096,256,0,s2>>>(pa2, pscal);
        zinit_kernel<<<2048,256,0,s2>>>(pa2, pscal, pz);
        float* zc = pz; float* zo = pz2;
        for (int it=0; it<6; it++) {
            GEMM(false,false,false,false,false,true,false,false, dim3(4,4,8), s2,
                 pa2, zc, F0, pxz, F0,F0,F0,F0, 256,256,256, 256,256,256, 65536,65536,65536, 1, 1.f,0.f,1.f);
            GEMM(false,false,false,false,false,true,false,false, dim3(4,4,8), s2,
                 pxz, pxz, F0, pt1, F0,F0,F0,F0, 256,256,256, 256,256,256, 65536,65536,65536, 1, 1.f,7.f,-1.f);
            GEMM(false,false,false,false,false,true,false,false, dim3(4,4,8), s2,
                 pxz, pt1, F0, pt2, F0,F0,F0,F0, 256,256,256, 256,256,256, 65536,65536,65536, 1, 1.f,15.f,-1.f);
            GEMM(false,false,false,false,false,true,false,false, dim3(4,4,8), s2,
                 zc, pt2, F0, zo, F0,F0,F0,F0, 256,256,256, 256,256,256, 65536,65536,65536, 1, 0.25f,13.f,-1.f);
            float* tmp=zc; zc=zo; zo=tmp;
        }

        // attn3 chain (s0): 2 heads per batch; softmax fused into a3v A-load
        for (int h0=0; h0<NH; h0+=2) {
            GEMM128(true,false,false,false,false,false, dim3(128,2,2), s0,
                    pql + h0*ML*DH, pqkv+512+h0*64, F0, ps3, F0,F0,F0,F0,
                    256,N_TOK,64, 64,QKV3,N_TOK, ML*DH,64,(long)ML*N_TOK);
            softmax_stats_kernel<<<2*ML,256,0,s0>>>(ps3, N_TOK, psm, psrv);
            GEMM(false,false,false,false,false,false,false,true, dim3(1,4,2*32), s0,
                 ps3, pqkv+1024+h0*64, F0, ppart, F0,F0,psm,psrv,
                 256,64,N_TOK, N_TOK,QKV3,64, (long)ML*N_TOK,64,ML*DH, 32, 1.f,0.f,1.f);
            reduce_part_kernel<<<(2*ML*DH+255)/256,256,0,s0>>>(ppart, pa3v + h0*ML*DH, 32, ML*DH, 2);
        }

        // ---- join ----
        cudaEventRecord(evJ, s2);
        cudaStreamWaitEvent(s0, evJ, 0);

        // W = pinv @ a3v  (batched over heads, split-K 4)
        GEMM(false,false,false,false,false,false,false,false, dim3(1,4,8*4), s0,
             zc, pa3v, F0, ppart, F0,F0,F0,F0,
             256,64,256, 256,64,64, 65536,ML*DH,ML*DH, 4, 1.f,0.f,1.f);
        reduce_part_kernel<<<(NH*ML*DH+255)/256,256,0,s0>>>(ppart, pW, 4, ML*DH, NH);

        // fused: q-slot of qkv <- softmax(q @ k_l^T) @ W
        attn1_kernel<<<dim3(512,NH),256,ATTN1_SMEM,s0>>>(pqkv, pkl, pW);
        // + depthwise residual conv of v
        conv_kernel<<<(N_TOK*DIMF)/256,256,0,s0>>>(pqkv, rk);
        // h += attn_out @ out_w + out_b
        GEMM128(false,true,false,true,false,false, dim3(4,128,1), s0,
                pqkv, ow, ob, ph, F0,F0,F0,F0, N_TOK,512,512, 1536,512,512, 0,0,0);
    }

    final_kernel<<<1,512,0,s0>>>(ph, norm_w, norm_b, clf_w, clf_b, out);
}